// round 14
// baseline (speedup 1.0000x reference)
#include <cuda_runtime.h>
#include <cuda_bf16.h>
#include <cuda_fp16.h>
#include <math.h>
#include <stdint.h>

#define B_ 8
#define T_ 2048
#define C_ 1024
#define H_ 64
#define CHUNK 8          // KV 64-tiles per attention CTA (= 4 super-tiles)

// Q post-RoPE, fp16 hi/lo; K post-RoPE fp16 (single); row-major [B*T][64]
__device__ __align__(16) __half g_Qhi[B_*T_*H_];
__device__ __align__(16) __half g_Qlo[B_*T_*H_];
__device__ __align__(16) __half g_Khi[B_*T_*H_];
// V transposed [B][64 h][T], fp16
__device__ __align__(16) __half g_VThi[B_*H_*T_];
// W split bf16 hi/lo, K-major [192][1024]
__device__ __align__(16) __nv_bfloat16 g_Bhi[192*1024];
__device__ __align__(16) __nv_bfloat16 g_Blo[192*1024];
// split-KV partials (qt >= 8 only): part = (b*32 + qt)*4 + chunk
// m tracked in base-2 scaled space (s * scale * log2e)
__device__ __align__(16) float g_Opart[B_*32*4*64*64];
__device__ float g_mpart[B_*32*4*64];
__device__ float g_lpart[B_*32*4*64];

__device__ __forceinline__ uint32_t smem_u32(const void* p) {
    uint32_t a;
    asm("{ .reg .u64 t; cvta.to.shared.u64 t, %1; cvt.u32.u64 %0, t; }" : "=r"(a) : "l"(p));
    return a;
}
__device__ __forceinline__ void ldmx4(uint32_t& r0, uint32_t& r1, uint32_t& r2, uint32_t& r3,
                                      uint32_t addr) {
    asm volatile("ldmatrix.sync.aligned.m8n8.x4.shared.b16 {%0,%1,%2,%3}, [%4];"
                 : "=r"(r0), "=r"(r1), "=r"(r2), "=r"(r3) : "r"(addr));
}
__device__ __forceinline__ void mma_bf16(float* c,
                                         uint32_t a0, uint32_t a1, uint32_t a2, uint32_t a3,
                                         uint32_t b0, uint32_t b1) {
    asm volatile("mma.sync.aligned.m16n8k16.row.col.f32.bf16.bf16.f32 "
                 "{%0,%1,%2,%3}, {%4,%5,%6,%7}, {%8,%9}, {%0,%1,%2,%3};"
                 : "+f"(c[0]), "+f"(c[1]), "+f"(c[2]), "+f"(c[3])
                 : "r"(a0), "r"(a1), "r"(a2), "r"(a3), "r"(b0), "r"(b1));
}
__device__ __forceinline__ void mma_f16(float* c,
                                        uint32_t a0, uint32_t a1, uint32_t a2, uint32_t a3,
                                        uint32_t b0, uint32_t b1) {
    asm volatile("mma.sync.aligned.m16n8k16.row.col.f32.f16.f16.f32 "
                 "{%0,%1,%2,%3}, {%4,%5,%6,%7}, {%8,%9}, {%0,%1,%2,%3};"
                 : "+f"(c[0]), "+f"(c[1]), "+f"(c[2]), "+f"(c[3])
                 : "r"(a0), "r"(a1), "r"(a2), "r"(a3), "r"(b0), "r"(b1));
}
__device__ __forceinline__ uint32_t bf16x2(float a, float b) {
    __nv_bfloat16 h0 = __float2bfloat16(a), h1 = __float2bfloat16(b);
    return (uint32_t)__bfloat16_as_ushort(h0) | ((uint32_t)__bfloat16_as_ushort(h1) << 16);
}
__device__ __forceinline__ float bf16lo_res(float v) {
    return v - __bfloat162float(__float2bfloat16(v));
}
__device__ __forceinline__ uint32_t h2pack(float a, float b) {
    __half2 h = __floats2half2_rn(a, b);
    return *reinterpret_cast<uint32_t*>(&h);
}
__device__ __forceinline__ float h_lo_res(float v) {
    return v - __half2float(__float2half_rn(v));
}
__device__ __forceinline__ float ex2f(float x) {
    float r; asm("ex2.approx.f32 %0, %1;" : "=f"(r) : "f"(x)); return r;
}
__device__ __forceinline__ uint32_t ex2_h2(uint32_t x) {
    uint32_t r; asm("ex2.approx.f16x2 %0, %1;" : "=r"(r) : "r"(x)); return r;
}
__device__ __forceinline__ float2 h2f2(uint32_t x) {
    __half2 h = *reinterpret_cast<__half2*>(&x);
    return __half22float2(h);
}
#define CP_A16(dst, src) \
    asm volatile("cp.async.cg.shared.global [%0], [%1], 16;" :: "r"(dst), "l"(src))
#define CP_COMMIT() asm volatile("cp.async.commit_group;" ::: "memory")
#define CP_WAIT0()  asm volatile("cp.async.wait_group 0;" ::: "memory")

// ---------------------------------------------------------------------------
// Prep: split W{q,k,v} into bf16 hi/lo, K-major [192][1024]
// ---------------------------------------------------------------------------
__global__ __launch_bounds__(256) void prep_B_kernel(
    const float* __restrict__ Wq, const float* __restrict__ Wk, const float* __restrict__ Wv)
{
    int idx = blockIdx.x * 256 + threadIdx.x;
    int n = idx >> 10, k = idx & 1023;
    const float* W = (n < 64) ? Wq : (n < 128) ? Wk : Wv;
    float v = W[k * 64 + (n & 63)];
    __nv_bfloat16 h = __float2bfloat16(v);
    g_Bhi[idx] = h;
    g_Blo[idx] = __float2bfloat16(v - __bfloat162float(h));
}

// ---------------------------------------------------------------------------
// Projection GEMM (HMMA bf16 hi/lo split). M=128 x N=192 per CTA, 16 warps.
// Epilogue: RoPE; Q fp16 hi/lo, K fp16, V fp16 transposed.
// ---------------------------------------------------------------------------
#define PA_STR 72
#define SM_AHI 0
#define SM_ALO (128*PA_STR*2)
#define SM_BHI (2*128*PA_STR*2)
#define SM_BLO (SM_BHI + 192*PA_STR*2)
#define SM_TOT (SM_BLO + 192*PA_STR*2)

__global__ __launch_bounds__(512) void proj_gemm_kernel(const float* __restrict__ x)
{
    extern __shared__ char smem[];
    const uint32_t sbase = smem_u32(smem);
    const int tid    = threadIdx.x;
    const int wid    = tid >> 5;
    const int lane   = tid & 31;
    const int warp_m = wid >> 2;
    const int warp_n = wid & 3;
    const int m0     = blockIdx.x * 128;

    uint32_t aOff[2], bOff[3];
    {
        int mlo = (lane >> 3) & 1, khi = (lane >> 4) & 1, r8 = lane & 7;
        #pragma unroll
        for (int mt = 0; mt < 2; mt++)
            aOff[mt] = (uint32_t)((warp_m*32 + mt*16 + mlo*8 + r8) * (PA_STR*2) + khi*16);
        #pragma unroll
        for (int p = 0; p < 3; p++)
            bOff[p] = (uint32_t)((warp_n*48 + p*16 + khi*8 + r8) * (PA_STR*2) + mlo*16);
    }

    float acc[2][6][4];
    #pragma unroll
    for (int mt = 0; mt < 2; mt++)
        #pragma unroll
        for (int nt = 0; nt < 6; nt++)
            #pragma unroll
            for (int q = 0; q < 4; q++) acc[mt][nt][q] = 0.f;

    #pragma unroll 1
    for (int c = 0; c < 16; c++) {
        const int kc = c * 64;
        if (c > 0) __syncthreads();

        #pragma unroll
        for (int it = tid; it < 2048; it += 512) {
            int r = it >> 4, q = it & 15;
            float4 f = *reinterpret_cast<const float4*>(x + (size_t)(m0 + r) * C_ + kc + q*4);
            uint32_t h0 = bf16x2(f.x, f.y), h1 = bf16x2(f.z, f.w);
            uint32_t l0 = bf16x2(bf16lo_res(f.x), bf16lo_res(f.y));
            uint32_t l1 = bf16x2(bf16lo_res(f.z), bf16lo_res(f.w));
            uint32_t off = (uint32_t)(r * (PA_STR*2) + q * 8);
            *reinterpret_cast<uint2*>(smem + SM_AHI + off) = make_uint2(h0, h1);
            *reinterpret_cast<uint2*>(smem + SM_ALO + off) = make_uint2(l0, l1);
        }
        #pragma unroll
        for (int it = tid; it < 1536; it += 512) {
            int n = it >> 3, s = it & 7;
            uint32_t off = (uint32_t)(n * (PA_STR*2) + s * 16);
            *reinterpret_cast<uint4*>(smem + SM_BHI + off) =
                *reinterpret_cast<const uint4*>(g_Bhi + (size_t)n * 1024 + kc + s*8);
            *reinterpret_cast<uint4*>(smem + SM_BLO + off) =
                *reinterpret_cast<const uint4*>(g_Blo + (size_t)n * 1024 + kc + s*8);
        }
        __syncthreads();

        #pragma unroll 1
        for (int pass = 0; pass < 3; pass++) {
            uint32_t aBase = sbase + ((pass < 2) ? SM_AHI : SM_ALO);
            uint32_t bBase = sbase + ((pass == 1) ? SM_BLO : SM_BHI);
            #pragma unroll
            for (int ks = 0; ks < 4; ks++) {
                uint32_t kb = (uint32_t)(ks * 32);
                uint32_t a[2][4];
                #pragma unroll
                for (int mt = 0; mt < 2; mt++)
                    ldmx4(a[mt][0], a[mt][1], a[mt][2], a[mt][3], aBase + aOff[mt] + kb);
                uint32_t b[6][2];
                #pragma unroll
                for (int p = 0; p < 3; p++) {
                    uint32_t r0, r1, r2, r3;
                    ldmx4(r0, r1, r2, r3, bBase + bOff[p] + kb);
                    b[p*2][0] = r0; b[p*2][1] = r1;
                    b[p*2+1][0] = r2; b[p*2+1][1] = r3;
                }
                #pragma unroll
                for (int mt = 0; mt < 2; mt++)
                    #pragma unroll
                    for (int nt = 0; nt < 6; nt++)
                        mma_bf16(acc[mt][nt], a[mt][0], a[mt][1], a[mt][2], a[mt][3],
                                 b[nt][0], b[nt][1]);
            }
        }
    }

    const int g  = lane >> 2;
    const int tq = lane & 3;
    #pragma unroll
    for (int mt = 0; mt < 2; mt++) {
        int row0 = m0 + warp_m*32 + mt*16 + g;
        int rows[2] = { row0, row0 + 8 };
        #pragma unroll
        for (int nt = 0; nt < 6; nt++) {
            int col = warp_n*48 + nt*8 + 2*tq;
            int mat = col >> 6;
            int col_in = col & 63;
            if (mat < 2) {
                int pi = col_in >> 1;
                float inv = powf(10000.f, -(float)pi * (1.f / 32.f));
                #pragma unroll
                for (int rg = 0; rg < 2; rg++) {
                    int t = rows[rg] & (T_ - 1);
                    float sn, cs;
                    sincosf((float)t * inv, &sn, &cs);
                    float a0 = acc[mt][nt][rg*2], a1 = acc[mt][nt][rg*2 + 1];
                    float v0 = a0*cs - a1*sn, v1 = a1*cs + a0*sn;
                    size_t base = (size_t)rows[rg] * H_ + col_in;
                    if (mat == 0) {
                        *reinterpret_cast<uint32_t*>(&g_Qhi[base]) = h2pack(v0, v1);
                        *reinterpret_cast<uint32_t*>(&g_Qlo[base]) =
                            h2pack(h_lo_res(v0), h_lo_res(v1));
                    } else {
                        *reinterpret_cast<uint32_t*>(&g_Khi[base]) = h2pack(v0, v1);
                    }
                }
            } else {
                #pragma unroll
                for (int rg = 0; rg < 2; rg++) {
                    int bb = rows[rg] >> 11, tt = rows[rg] & (T_ - 1);
                    #pragma unroll
                    for (int e = 0; e < 2; e++) {
                        float v = acc[mt][nt][rg*2 + e];
                        size_t idx = ((size_t)bb * H_ + (col_in + e)) * T_ + tt;
                        g_VThi[idx] = __float2half_rn(v);
                    }
                }
            }
        }
    }
}

// ---------------------------------------------------------------------------
// Split-KV attention partial, 128-wide KV SUPER-TILES:
// per iteration stage K0,K1,V0,V1 (2 sub-tiles), S = Qh*Kh + Ql*Kh over 128
// cols, ONE base-2 softmax per 128 cols (ex2.f16x2 -> packed P), PV = Ph*Vh.
// Halves iteration count / barriers / softmax reductions vs 64-wide.
// smem: Q hi/lo + K0 K1 V0 V1 = 6 tiles = 55296B -> 4 CTAs/SM. Synchronous
// staging (double-buffering measured free at this occupancy).
// ---------------------------------------------------------------------------
#define ASTR   72
#define TILE_B (64*ASTR*2)
#define AQHI   0
#define AQLO   TILE_B
#define AKV    (2*TILE_B)           // K0, K1, V0, V1
#define ASM_TOT (6*TILE_B)          // 55296

#define SCALE_L2E 0.1803368801f     // 0.125 * log2(e)
#define MASK_NEG  (-3.0e4f)

// stage super-tile st: K 64-tiles (2st, 2st+1) and matching V^T slices
__device__ __forceinline__ void stage_kv2(uint32_t sbase_, int b, int st, int tid) {
    const __half* Kh = g_Khi + ((size_t)b * T_ + st*128) * H_;
    #pragma unroll
    for (int it = tid; it < 1024; it += 128) {
        int r = it >> 3, s = it & 7;          // r: 0..127 across both sub-tiles
        int sub = r >> 6, rr = r & 63;
        uint32_t off = (uint32_t)(rr * (ASTR*2) + s*16);
        CP_A16(sbase_ + AKV + sub*TILE_B + off, Kh + r*64 + s*8);
        size_t vsrc = ((size_t)b * H_ + rr) * T_ + (size_t)(2*st + sub)*64 + s*8;
        CP_A16(sbase_ + AKV + (2 + sub)*TILE_B + off, g_VThi + vsrc);
    }
}

__global__ __launch_bounds__(128, 4) void attn_part_kernel(float* __restrict__ out)
{
    extern __shared__ char smem[];
    const uint32_t sbase = smem_u32(smem);
    const int tid  = threadIdx.x;
    const int wid  = tid >> 5;
    const int lane = tid & 31;
    const int b    = blockIdx.y;
    const int r8   = lane & 7;
    const int mlo  = (lane >> 3) & 1;
    const int khi  = (lane >> 4) & 1;
    const int g    = lane >> 2;
    const int tq   = lane & 3;

    int qt = 0, chunk = 0;
    {
        int bx = blockIdx.x, acc = 0;
        #pragma unroll 1
        for (int q = 0; q < 32; q++) {
            int nc = (q >> 3) + 1;
            if (bx < acc + nc) { qt = q; chunk = bx - acc; break; }
            acc += nc;
        }
    }
    const int st0 = chunk * 4;                       // super-tiles of 128
    const int stD = qt >> 1;                         // diagonal super-tile
    const int st1 = (st0 + 3 < stD) ? (st0 + 3) : stD;

    const uint32_t aRowOff = (uint32_t)((wid*16 + mlo*8 + r8) * (ASTR*2) + khi*16);
    uint32_t bRowOff[4];
    #pragma unroll
    for (int p = 0; p < 4; p++)
        bRowOff[p] = (uint32_t)((p*16 + khi*8 + r8) * (ASTR*2) + mlo*16);

    // stage Q + first super-tile
    {
        const __half* Qh = g_Qhi + ((size_t)b * T_ + qt*64) * H_;
        const __half* Ql = g_Qlo + ((size_t)b * T_ + qt*64) * H_;
        #pragma unroll
        for (int it = tid; it < 512; it += 128) {
            int r = it >> 3, s = it & 7;
            uint32_t off = (uint32_t)(r * (ASTR*2) + s*16);
            CP_A16(sbase + AQHI + off, Qh + r*64 + s*8);
            CP_A16(sbase + AQLO + off, Ql + r*64 + s*8);
        }
        stage_kv2(sbase, b, st0, tid);
        CP_COMMIT();
    }
    CP_WAIT0();
    __syncthreads();

    float m0r = MASK_NEG, m1r = MASK_NEG, l0 = 0.f, l1 = 0.f;
    float o[8][4];
    #pragma unroll
    for (int nt = 0; nt < 8; nt++)
        #pragma unroll
        for (int q = 0; q < 4; q++) o[nt][q] = 0.f;

    #pragma unroll 1
    for (int st = st0; st <= st1; st++) {
        // ---- S over 128 cols (2 passes: Qh*Kh + Ql*Kh) ----
        float s_[16][4];
        #pragma unroll
        for (int nt = 0; nt < 16; nt++)
            #pragma unroll
            for (int q = 0; q < 4; q++) s_[nt][q] = 0.f;

        #pragma unroll
        for (int ks = 0; ks < 4; ks++) {
            uint32_t kb = (uint32_t)(ks * 32);
            uint32_t qh0, qh1, qh2, qh3, ql0, ql1, ql2, ql3;
            ldmx4(qh0, qh1, qh2, qh3, sbase + AQHI + aRowOff + kb);
            ldmx4(ql0, ql1, ql2, ql3, sbase + AQLO + aRowOff + kb);
            #pragma unroll
            for (int sub = 0; sub < 2; sub++) {
                #pragma unroll
                for (int p = 0; p < 4; p++) {
                    uint32_t kh0, kh1, kh2, kh3;
                    ldmx4(kh0, kh1, kh2, kh3,
                          sbase + AKV + sub*TILE_B + bRowOff[p] + kb);
                    int nt = sub*8 + 2*p;
                    mma_f16(s_[nt],   qh0, qh1, qh2, qh3, kh0, kh1);
                    mma_f16(s_[nt+1], qh0, qh1, qh2, qh3, kh2, kh3);
                    mma_f16(s_[nt],   ql0, ql1, ql2, ql3, kh0, kh1);
                    mma_f16(s_[nt+1], ql0, ql1, ql2, ql3, kh2, kh3);
                }
            }
        }

        // scale into base-2 space + causal mask on the diagonal super-tile
        #pragma unroll
        for (int nt = 0; nt < 16; nt++)
            #pragma unroll
            for (int q = 0; q < 4; q++) s_[nt][q] *= SCALE_L2E;
        if (st == stD) {
            int qr0 = qt*64 + wid*16 + g;
            #pragma unroll
            for (int nt = 0; nt < 16; nt++) {
                int kc0 = st*128 + nt*8 + 2*tq;
                if (kc0     > qr0)     s_[nt][0] = MASK_NEG;
                if (kc0 + 1 > qr0)     s_[nt][1] = MASK_NEG;
                if (kc0     > qr0 + 8) s_[nt][2] = MASK_NEG;
                if (kc0 + 1 > qr0 + 8) s_[nt][3] = MASK_NEG;
            }
        }

        // ---- ONE online softmax per 128 cols ----
        float mx0 = MASK_NEG, mx1 = MASK_NEG;
        #pragma unroll
        for (int nt = 0; nt < 16; nt++) {
            mx0 = fmaxf(mx0, fmaxf(s_[nt][0], s_[nt][1]));
            mx1 = fmaxf(mx1, fmaxf(s_[nt][2], s_[nt][3]));
        }
        mx0 = fmaxf(mx0, __shfl_xor_sync(0xffffffffu, mx0, 1));
        mx0 = fmaxf(mx0, __shfl_xor_sync(0xffffffffu, mx0, 2));
        mx1 = fmaxf(mx1, __shfl_xor_sync(0xffffffffu, mx1, 1));
        mx1 = fmaxf(mx1, __shfl_xor_sync(0xffffffffu, mx1, 2));
        float mn0 = fmaxf(m0r, mx0), mn1 = fmaxf(m1r, mx1);
        float al0 = ex2f(m0r - mn0), al1 = ex2f(m1r - mn1);

        uint32_t pe[16][2];
        float rs0 = 0.f, rs1 = 0.f;
        #pragma unroll
        for (int nt = 0; nt < 16; nt++) {
            pe[nt][0] = ex2_h2(h2pack(s_[nt][0] - mn0, s_[nt][1] - mn0));
            pe[nt][1] = ex2_h2(h2pack(s_[nt][2] - mn1, s_[nt][3] - mn1));
            float2 f0 = h2f2(pe[nt][0]);
            float2 f1 = h2f2(pe[nt][1]);
            rs0 += f0.x + f0.y;
            rs1 += f1.x + f1.y;
        }
        rs0 += __shfl_xor_sync(0xffffffffu, rs0, 1);
        rs0 += __shfl_xor_sync(0xffffffffu, rs0, 2);
        rs1 += __shfl_xor_sync(0xffffffffu, rs1, 1);
        rs1 += __shfl_xor_sync(0xffffffffu, rs1, 2);
        l0 = l0 * al0 + rs0;  l1 = l1 * al1 + rs1;
        m0r = mn0;  m1r = mn1;
        #pragma unroll
        for (int nt = 0; nt < 8; nt++) {
            o[nt][0] *= al0; o[nt][1] *= al0;
            o[nt][2] *= al1; o[nt][3] *= al1;
        }

        // ---- O += P V over both sub-tiles ----
        #pragma unroll
        for (int kk = 0; kk < 8; kk++) {
            int sub = kk >> 2;
            uint32_t kb = (uint32_t)((kk & 3) * 32);
            uint32_t vbase = sbase + AKV + (2 + sub)*TILE_B;
            int nt = sub*8 + 2*(kk & 3);
            #pragma unroll
            for (int p = 0; p < 4; p++) {
                uint32_t vh0, vh1, vh2, vh3;
                ldmx4(vh0, vh1, vh2, vh3, vbase + bRowOff[p] + kb);
                mma_f16(o[2*p],   pe[nt][0], pe[nt][1], pe[nt+1][0], pe[nt+1][1], vh0, vh1);
                mma_f16(o[2*p+1], pe[nt][0], pe[nt][1], pe[nt+1][0], pe[nt+1][1], vh2, vh3);
            }
        }

        // rotate single buffer
        __syncthreads();
        if (st < st1) {
            stage_kv2(sbase, b, st + 1, tid);
            CP_COMMIT();
            CP_WAIT0();
            __syncthreads();
        }
    }

    const int row0 = wid*16 + g;
    if (qt < 8) {
        float rc0 = 1.f / l0, rc1 = 1.f / l1;
        #pragma unroll
        for (int nt = 0; nt < 8; nt++) {
            int col = nt*8 + 2*tq;
            *reinterpret_cast<float2*>(&out[((size_t)b*T_ + qt*64 + row0) * H_ + col]) =
                make_float2(o[nt][0]*rc0, o[nt][1]*rc0);
            *reinterpret_cast<float2*>(&out[((size_t)b*T_ + qt*64 + row0 + 8) * H_ + col]) =
                make_float2(o[nt][2]*rc1, o[nt][3]*rc1);
        }
    } else {
        const int part = (b*32 + qt)*4 + chunk;
        float* Op = g_Opart + (size_t)part * 64 * 64;
        #pragma unroll
        for (int nt = 0; nt < 8; nt++) {
            int col = nt*8 + 2*tq;
            *reinterpret_cast<float2*>(&Op[(row0)     * 64 + col]) = make_float2(o[nt][0], o[nt][1]);
            *reinterpret_cast<float2*>(&Op[(row0 + 8) * 64 + col]) = make_float2(o[nt][2], o[nt][3]);
        }
        if (tq == 0) {
            g_mpart[part*64 + row0]     = m0r;
            g_mpart[part*64 + row0 + 8] = m1r;
            g_lpart[part*64 + row0]     = l0;
            g_lpart[part*64 + row0 + 8] = l1;
        }
    }
}

// ---------------------------------------------------------------------------
// Merge: combine chunk partials per (b, qt) for qt >= 8 (base-2 weights).
// ---------------------------------------------------------------------------
__global__ __launch_bounds__(256) void attn_merge_kernel(float* __restrict__ out)
{
    const int qt = blockIdx.x + 8, b = blockIdx.y;
    const int nc = (qt >> 3) + 1;
    const int r  = (int)blockIdx.z * 16 + (threadIdx.x >> 4);  // 0..63
    const int cb = (threadIdx.x & 15) * 4;
    const int pbase = (b*32 + qt)*4;

    float m = -3.0e4f;
    #pragma unroll
    for (int c = 0; c < 4; c++)
        if (c < nc) m = fmaxf(m, g_mpart[(pbase + c)*64 + r]);
    float w[4];
    float l = 0.f;
    #pragma unroll
    for (int c = 0; c < 4; c++) {
        if (c < nc) {
            w[c] = ex2f(g_mpart[(pbase + c)*64 + r] - m);
            l += w[c] * g_lpart[(pbase + c)*64 + r];
        } else w[c] = 0.f;
    }
    float inv = 1.f / l;

    float4 acc = make_float4(0.f, 0.f, 0.f, 0.f);
    #pragma unroll
    for (int c = 0; c < 4; c++) {
        if (c < nc) {
            float4 v = *reinterpret_cast<const float4*>(
                &g_Opart[((size_t)(pbase + c)*64 + r)*64 + cb]);
            acc.x += w[c]*v.x; acc.y += w[c]*v.y;
            acc.z += w[c]*v.z; acc.w += w[c]*v.w;
        }
    }
    acc.x *= inv; acc.y *= inv; acc.z *= inv; acc.w *= inv;
    *reinterpret_cast<float4*>(&out[((size_t)b*T_ + qt*64 + r)*H_ + cb]) = acc;
}

extern "C" void kernel_launch(void* const* d_in, const int* in_sizes, int n_in,
                              void* d_out, int out_size)
{
    const float* x  = (const float*)d_in[0];
    const float* Wq = (const float*)d_in[1];
    const float* Wk = (const float*)d_in[2];
    const float* Wv = (const float*)d_in[3];
    float* out = (float*)d_out;

    cudaFuncSetAttribute(proj_gemm_kernel,
                         cudaFuncAttributeMaxDynamicSharedMemorySize, SM_TOT);
    cudaFuncSetAttribute(attn_part_kernel,
                         cudaFuncAttributeMaxDynamicSharedMemorySize, ASM_TOT);

    prep_B_kernel<<<(192 * 1024) / 256, 256>>>(Wq, Wk, Wv);
    proj_gemm_kernel<<<(B_ * T_) / 128, 512, SM_TOT>>>(x);
    attn_part_kernel<<<dim3(80, B_), 128, ASM_TOT>>>(out);
    attn_merge_kernel<<<dim3(24, B_, 4), 256>>>(out);
}

// round 15
// speedup vs baseline: 1.0342x; 1.0342x over previous
#include <cuda_runtime.h>
#include <cuda_bf16.h>
#include <cuda_fp16.h>
#include <math.h>
#include <stdint.h>

#define B_ 8
#define T_ 2048
#define C_ 1024
#define H_ 64

// Q post-RoPE, fp16 hi/lo; K post-RoPE fp16; row-major [B*T][64]
__device__ __align__(16) __half g_Qhi[B_*T_*H_];
__device__ __align__(16) __half g_Qlo[B_*T_*H_];
__device__ __align__(16) __half g_Khi[B_*T_*H_];
// V transposed [B][64 h][T], fp16
__device__ __align__(16) __half g_VThi[B_*H_*T_];
// W split bf16 hi/lo, K-major [192][1024]
__device__ __align__(16) __nv_bfloat16 g_Bhi[192*1024];
__device__ __align__(16) __nv_bfloat16 g_Blo[192*1024];
// split-KV partials (qp >= 4 only): part = (b*16 + qp)*4 + chunk, 128 rows each
// m tracked in base-2 scaled space (s * scale * log2e)
__device__ __align__(16) float g_Opart[B_*16*4*128*64];
__device__ float g_mpart[B_*16*4*128];
__device__ float g_lpart[B_*16*4*128];

__device__ __forceinline__ uint32_t smem_u32(const void* p) {
    uint32_t a;
    asm("{ .reg .u64 t; cvta.to.shared.u64 t, %1; cvt.u32.u64 %0, t; }" : "=r"(a) : "l"(p));
    return a;
}
__device__ __forceinline__ void ldmx4(uint32_t& r0, uint32_t& r1, uint32_t& r2, uint32_t& r3,
                                      uint32_t addr) {
    asm volatile("ldmatrix.sync.aligned.m8n8.x4.shared.b16 {%0,%1,%2,%3}, [%4];"
                 : "=r"(r0), "=r"(r1), "=r"(r2), "=r"(r3) : "r"(addr));
}
__device__ __forceinline__ void mma_bf16(float* c,
                                         uint32_t a0, uint32_t a1, uint32_t a2, uint32_t a3,
                                         uint32_t b0, uint32_t b1) {
    asm volatile("mma.sync.aligned.m16n8k16.row.col.f32.bf16.bf16.f32 "
                 "{%0,%1,%2,%3}, {%4,%5,%6,%7}, {%8,%9}, {%0,%1,%2,%3};"
                 : "+f"(c[0]), "+f"(c[1]), "+f"(c[2]), "+f"(c[3])
                 : "r"(a0), "r"(a1), "r"(a2), "r"(a3), "r"(b0), "r"(b1));
}
__device__ __forceinline__ void mma_f16(float* c,
                                        uint32_t a0, uint32_t a1, uint32_t a2, uint32_t a3,
                                        uint32_t b0, uint32_t b1) {
    asm volatile("mma.sync.aligned.m16n8k16.row.col.f32.f16.f16.f32 "
                 "{%0,%1,%2,%3}, {%4,%5,%6,%7}, {%8,%9}, {%0,%1,%2,%3};"
                 : "+f"(c[0]), "+f"(c[1]), "+f"(c[2]), "+f"(c[3])
                 : "r"(a0), "r"(a1), "r"(a2), "r"(a3), "r"(b0), "r"(b1));
}
__device__ __forceinline__ uint32_t bf16x2(float a, float b) {
    __nv_bfloat16 h0 = __float2bfloat16(a), h1 = __float2bfloat16(b);
    return (uint32_t)__bfloat16_as_ushort(h0) | ((uint32_t)__bfloat16_as_ushort(h1) << 16);
}
__device__ __forceinline__ float bf16lo_res(float v) {
    return v - __bfloat162float(__float2bfloat16(v));
}
__device__ __forceinline__ uint32_t h2pack(float a, float b) {
    __half2 h = __floats2half2_rn(a, b);
    return *reinterpret_cast<uint32_t*>(&h);
}
__device__ __forceinline__ float h_lo_res(float v) {
    return v - __half2float(__float2half_rn(v));
}
__device__ __forceinline__ float ex2f(float x) {
    float r; asm("ex2.approx.f32 %0, %1;" : "=f"(r) : "f"(x)); return r;
}
__device__ __forceinline__ uint32_t ex2_h2(uint32_t x) {
    uint32_t r; asm("ex2.approx.f16x2 %0, %1;" : "=r"(r) : "r"(x)); return r;
}
__device__ __forceinline__ float2 h2f2(uint32_t x) {
    __half2 h = *reinterpret_cast<__half2*>(&x);
    return __half22float2(h);
}
#define CP_A16(dst, src) \
    asm volatile("cp.async.cg.shared.global [%0], [%1], 16;" :: "r"(dst), "l"(src))
#define CP_COMMIT() asm volatile("cp.async.commit_group;" ::: "memory")
#define CP_WAIT0()  asm volatile("cp.async.wait_group 0;" ::: "memory")
#define CP_WAIT1()  asm volatile("cp.async.wait_group 1;" ::: "memory")

// ---------------------------------------------------------------------------
// Prep: split W{q,k,v} into bf16 hi/lo, K-major [192][1024]
// ---------------------------------------------------------------------------
__global__ __launch_bounds__(256) void prep_B_kernel(
    const float* __restrict__ Wq, const float* __restrict__ Wk, const float* __restrict__ Wv)
{
    int idx = blockIdx.x * 256 + threadIdx.x;
    int n = idx >> 10, k = idx & 1023;
    const float* W = (n < 64) ? Wq : (n < 128) ? Wk : Wv;
    float v = W[k * 64 + (n & 63)];
    __nv_bfloat16 h = __float2bfloat16(v);
    g_Bhi[idx] = h;
    g_Blo[idx] = __float2bfloat16(v - __bfloat162float(h));
}

// ---------------------------------------------------------------------------
// Projection GEMM (HMMA bf16 hi/lo split). M=128 x N=192 per CTA, 16 warps.
// Epilogue: RoPE; Q fp16 hi/lo, K fp16, V fp16 transposed.
// ---------------------------------------------------------------------------
#define PA_STR 72
#define SM_AHI 0
#define SM_ALO (128*PA_STR*2)
#define SM_BHI (2*128*PA_STR*2)
#define SM_BLO (SM_BHI + 192*PA_STR*2)
#define SM_TOT (SM_BLO + 192*PA_STR*2)

__global__ __launch_bounds__(512) void proj_gemm_kernel(const float* __restrict__ x)
{
    extern __shared__ char smem[];
    const uint32_t sbase = smem_u32(smem);
    const int tid    = threadIdx.x;
    const int wid    = tid >> 5;
    const int lane   = tid & 31;
    const int warp_m = wid >> 2;
    const int warp_n = wid & 3;
    const int m0     = blockIdx.x * 128;

    uint32_t aOff[2], bOff[3];
    {
        int mlo = (lane >> 3) & 1, khi = (lane >> 4) & 1, r8 = lane & 7;
        #pragma unroll
        for (int mt = 0; mt < 2; mt++)
            aOff[mt] = (uint32_t)((warp_m*32 + mt*16 + mlo*8 + r8) * (PA_STR*2) + khi*16);
        #pragma unroll
        for (int p = 0; p < 3; p++)
            bOff[p] = (uint32_t)((warp_n*48 + p*16 + khi*8 + r8) * (PA_STR*2) + mlo*16);
    }

    float acc[2][6][4];
    #pragma unroll
    for (int mt = 0; mt < 2; mt++)
        #pragma unroll
        for (int nt = 0; nt < 6; nt++)
            #pragma unroll
            for (int q = 0; q < 4; q++) acc[mt][nt][q] = 0.f;

    #pragma unroll 1
    for (int c = 0; c < 16; c++) {
        const int kc = c * 64;
        if (c > 0) __syncthreads();

        #pragma unroll
        for (int it = tid; it < 2048; it += 512) {
            int r = it >> 4, q = it & 15;
            float4 f = *reinterpret_cast<const float4*>(x + (size_t)(m0 + r) * C_ + kc + q*4);
            uint32_t h0 = bf16x2(f.x, f.y), h1 = bf16x2(f.z, f.w);
            uint32_t l0 = bf16x2(bf16lo_res(f.x), bf16lo_res(f.y));
            uint32_t l1 = bf16x2(bf16lo_res(f.z), bf16lo_res(f.w));
            uint32_t off = (uint32_t)(r * (PA_STR*2) + q * 8);
            *reinterpret_cast<uint2*>(smem + SM_AHI + off) = make_uint2(h0, h1);
            *reinterpret_cast<uint2*>(smem + SM_ALO + off) = make_uint2(l0, l1);
        }
        #pragma unroll
        for (int it = tid; it < 1536; it += 512) {
            int n = it >> 3, s = it & 7;
            uint32_t off = (uint32_t)(n * (PA_STR*2) + s * 16);
            *reinterpret_cast<uint4*>(smem + SM_BHI + off) =
                *reinterpret_cast<const uint4*>(g_Bhi + (size_t)n * 1024 + kc + s*8);
            *reinterpret_cast<uint4*>(smem + SM_BLO + off) =
                *reinterpret_cast<const uint4*>(g_Blo + (size_t)n * 1024 + kc + s*8);
        }
        __syncthreads();

        #pragma unroll 1
        for (int pass = 0; pass < 3; pass++) {
            uint32_t aBase = sbase + ((pass < 2) ? SM_AHI : SM_ALO);
            uint32_t bBase = sbase + ((pass == 1) ? SM_BLO : SM_BHI);
            #pragma unroll
            for (int ks = 0; ks < 4; ks++) {
                uint32_t kb = (uint32_t)(ks * 32);
                uint32_t a[2][4];
                #pragma unroll
                for (int mt = 0; mt < 2; mt++)
                    ldmx4(a[mt][0], a[mt][1], a[mt][2], a[mt][3], aBase + aOff[mt] + kb);
                uint32_t b[6][2];
                #pragma unroll
                for (int p = 0; p < 3; p++) {
                    uint32_t r0, r1, r2, r3;
                    ldmx4(r0, r1, r2, r3, bBase + bOff[p] + kb);
                    b[p*2][0] = r0; b[p*2][1] = r1;
                    b[p*2+1][0] = r2; b[p*2+1][1] = r3;
                }
                #pragma unroll
                for (int mt = 0; mt < 2; mt++)
                    #pragma unroll
                    for (int nt = 0; nt < 6; nt++)
                        mma_bf16(acc[mt][nt], a[mt][0], a[mt][1], a[mt][2], a[mt][3],
                                 b[nt][0], b[nt][1]);
            }
        }
    }

    const int g  = lane >> 2;
    const int tq = lane & 3;
    #pragma unroll
    for (int mt = 0; mt < 2; mt++) {
        int row0 = m0 + warp_m*32 + mt*16 + g;
        int rows[2] = { row0, row0 + 8 };
        #pragma unroll
        for (int nt = 0; nt < 6; nt++) {
            int col = warp_n*48 + nt*8 + 2*tq;
            int mat = col >> 6;
            int col_in = col & 63;
            if (mat < 2) {
                int pi = col_in >> 1;
                float inv = powf(10000.f, -(float)pi * (1.f / 32.f));
                #pragma unroll
                for (int rg = 0; rg < 2; rg++) {
                    int t = rows[rg] & (T_ - 1);
                    float sn, cs;
                    sincosf((float)t * inv, &sn, &cs);
                    float a0 = acc[mt][nt][rg*2], a1 = acc[mt][nt][rg*2 + 1];
                    float v0 = a0*cs - a1*sn, v1 = a1*cs + a0*sn;
                    size_t base = (size_t)rows[rg] * H_ + col_in;
                    if (mat == 0) {
                        *reinterpret_cast<uint32_t*>(&g_Qhi[base]) = h2pack(v0, v1);
                        *reinterpret_cast<uint32_t*>(&g_Qlo[base]) =
                            h2pack(h_lo_res(v0), h_lo_res(v1));
                    } else {
                        *reinterpret_cast<uint32_t*>(&g_Khi[base]) = h2pack(v0, v1);
                    }
                }
            } else {
                #pragma unroll
                for (int rg = 0; rg < 2; rg++) {
                    int bb = rows[rg] >> 11, tt = rows[rg] & (T_ - 1);
                    #pragma unroll
                    for (int e = 0; e < 2; e++) {
                        float v = acc[mt][nt][rg*2 + e];
                        size_t idx = ((size_t)bb * H_ + (col_in + e)) * T_ + tt;
                        g_VThi[idx] = __float2half_rn(v);
                    }
                }
            }
        }
    }
}

// ---------------------------------------------------------------------------
// Split-KV attention partial, 128 QUERY ROWS per CTA (8 warps, 16 rows/warp).
// Per-warp math identical to the proven 4-warp version (register-neutral):
// S = Qh*Kh + Ql*Kh; base-2 softmax via ex2.f16x2 (P packed fp16); PV = Ph*Vh.
// KV staging/barriers amortized over 2x query rows; double-buffered cp.async.
// smem: Q hi/lo (128 rows = 4 tiles) + 2x(K,V) = 8 tiles = 73728B -> 2 CTAs/SM.
// qp<4 (single chunk) writes output directly; qp>=4 emits partials for merge.
// ---------------------------------------------------------------------------
#define ASTR   72
#define TILE_B (64*ASTR*2)
#define AQHI   0
#define AQLO   (2*TILE_B)
#define AKV0   (4*TILE_B)           // K, V (buffer 0)
#define AKV1   (6*TILE_B)           // K, V (buffer 1)
#define ASM_TOT (8*TILE_B)          // 73728

#define SCALE_L2E 0.1803368801f     // 0.125 * log2(e)
#define MASK_NEG  (-3.0e4f)

__device__ __forceinline__ void stage_kv(uint32_t sdst, int b, int kt, int tid) {
    const __half* Kh = g_Khi + ((size_t)b * T_ + kt*64) * H_;
    #pragma unroll
    for (int it = tid; it < 512; it += 256) {
        int r = it >> 3, s = it & 7;
        uint32_t off = (uint32_t)(r * (ASTR*2) + s*16);
        CP_A16(sdst + off, Kh + r*64 + s*8);
        size_t vsrc = ((size_t)b * H_ + r) * T_ + kt*64 + s*8;
        CP_A16(sdst + TILE_B + off, g_VThi + vsrc);
    }
}

__global__ __launch_bounds__(256, 2) void attn_part_kernel(float* __restrict__ out)
{
    extern __shared__ char smem[];
    const uint32_t sbase = smem_u32(smem);
    const int tid  = threadIdx.x;
    const int wid  = tid >> 5;      // 0..7: q rows wid*16..+15
    const int lane = tid & 31;
    const int b    = blockIdx.y;
    const int r8   = lane & 7;
    const int mlo  = (lane >> 3) & 1;
    const int khi  = (lane >> 4) & 1;
    const int g    = lane >> 2;
    const int tq   = lane & 3;

    // decode (qp, chunk): qp has (2qp+9)>>3 chunks; total 40 per batch
    int qp = 0, chunk = 0;
    {
        int bx = blockIdx.x, acc = 0;
        #pragma unroll 1
        for (int q = 0; q < 16; q++) {
            int nc = (2*q + 9) >> 3;
            if (bx < acc + nc) { qp = q; chunk = bx - acc; break; }
            acc += nc;
        }
    }
    const int nchunks = (2*qp + 9) >> 3;
    const int kt0 = chunk * 8;
    const int ktmax = 2*qp + 1;
    const int kt1 = (kt0 + 7 < ktmax) ? (kt0 + 7) : ktmax;

    const uint32_t aRowOff = (uint32_t)((wid*16 + mlo*8 + r8) * (ASTR*2) + khi*16);
    uint32_t bRowOff[4];
    #pragma unroll
    for (int p = 0; p < 4; p++)
        bRowOff[p] = (uint32_t)((p*16 + khi*8 + r8) * (ASTR*2) + mlo*16);

    // stage Q (128 rows, hi/lo) + first KV tile, one group
    {
        const __half* Qh = g_Qhi + ((size_t)b * T_ + qp*128) * H_;
        const __half* Ql = g_Qlo + ((size_t)b * T_ + qp*128) * H_;
        #pragma unroll
        for (int it = tid; it < 1024; it += 256) {
            int r = it >> 3, s = it & 7;
            uint32_t off = (uint32_t)(r * (ASTR*2) + s*16);
            CP_A16(sbase + AQHI + off, Qh + r*64 + s*8);
            CP_A16(sbase + AQLO + off, Ql + r*64 + s*8);
        }
        stage_kv(sbase + AKV0, b, kt0, tid);
        CP_COMMIT();
    }

    float m0r = MASK_NEG, m1r = MASK_NEG, l0 = 0.f, l1 = 0.f;
    float o[8][4];
    #pragma unroll
    for (int nt = 0; nt < 8; nt++)
        #pragma unroll
        for (int q = 0; q < 4; q++) o[nt][q] = 0.f;

    #pragma unroll 1
    for (int kt = kt0; kt <= kt1; kt++) {
        const uint32_t kvb = sbase + (((kt - kt0) & 1) ? AKV1 : AKV0);

        if (kt < kt1) {
            stage_kv(sbase + (((kt + 1 - kt0) & 1) ? AKV1 : AKV0), b, kt + 1, tid);
            CP_COMMIT();
            CP_WAIT1();
        } else {
            CP_WAIT0();
        }
        __syncthreads();

        // ---- S = Q K^T (2 passes: Qh*Kh + Ql*Kh) ----
        float s_[8][4];
        #pragma unroll
        for (int nt = 0; nt < 8; nt++)
            #pragma unroll
            for (int q = 0; q < 4; q++) s_[nt][q] = 0.f;

        #pragma unroll
        for (int ks = 0; ks < 4; ks++) {
            uint32_t kb = (uint32_t)(ks * 32);
            uint32_t qh0, qh1, qh2, qh3, ql0, ql1, ql2, ql3;
            ldmx4(qh0, qh1, qh2, qh3, sbase + AQHI + aRowOff + kb);
            ldmx4(ql0, ql1, ql2, ql3, sbase + AQLO + aRowOff + kb);
            #pragma unroll
            for (int p = 0; p < 4; p++) {
                uint32_t kh0, kh1, kh2, kh3;
                ldmx4(kh0, kh1, kh2, kh3, kvb + bRowOff[p] + kb);
                mma_f16(s_[2*p],   qh0, qh1, qh2, qh3, kh0, kh1);
                mma_f16(s_[2*p+1], qh0, qh1, qh2, qh3, kh2, kh3);
                mma_f16(s_[2*p],   ql0, ql1, ql2, ql3, kh0, kh1);
                mma_f16(s_[2*p+1], ql0, ql1, ql2, ql3, kh2, kh3);
            }
        }

        // base-2 scale + causal mask (needed only on the last two tiles)
        #pragma unroll
        for (int nt = 0; nt < 8; nt++)
            #pragma unroll
            for (int q = 0; q < 4; q++) s_[nt][q] *= SCALE_L2E;
        if (kt >= 2*qp) {
            int qr0 = qp*128 + wid*16 + g;
            #pragma unroll
            for (int nt = 0; nt < 8; nt++) {
                int kc0 = kt*64 + nt*8 + 2*tq;
                if (kc0     > qr0)     s_[nt][0] = MASK_NEG;
                if (kc0 + 1 > qr0)     s_[nt][1] = MASK_NEG;
                if (kc0     > qr0 + 8) s_[nt][2] = MASK_NEG;
                if (kc0 + 1 > qr0 + 8) s_[nt][3] = MASK_NEG;
            }
        }

        // ---- online softmax (base-2; p emerges packed fp16) ----
        float mx0 = MASK_NEG, mx1 = MASK_NEG;
        #pragma unroll
        for (int nt = 0; nt < 8; nt++) {
            mx0 = fmaxf(mx0, fmaxf(s_[nt][0], s_[nt][1]));
            mx1 = fmaxf(mx1, fmaxf(s_[nt][2], s_[nt][3]));
        }
        mx0 = fmaxf(mx0, __shfl_xor_sync(0xffffffffu, mx0, 1));
        mx0 = fmaxf(mx0, __shfl_xor_sync(0xffffffffu, mx0, 2));
        mx1 = fmaxf(mx1, __shfl_xor_sync(0xffffffffu, mx1, 1));
        mx1 = fmaxf(mx1, __shfl_xor_sync(0xffffffffu, mx1, 2));
        float mn0 = fmaxf(m0r, mx0), mn1 = fmaxf(m1r, mx1);
        float al0 = ex2f(m0r - mn0), al1 = ex2f(m1r - mn1);

        uint32_t pe[8][2];
        float rs0 = 0.f, rs1 = 0.f;
        #pragma unroll
        for (int nt = 0; nt < 8; nt++) {
            pe[nt][0] = ex2_h2(h2pack(s_[nt][0] - mn0, s_[nt][1] - mn0));
            pe[nt][1] = ex2_h2(h2pack(s_[nt][2] - mn1, s_[nt][3] - mn1));
            float2 f0 = h2f2(pe[nt][0]);
            float2 f1 = h2f2(pe[nt][1]);
            rs0 += f0.x + f0.y;
            rs1 += f1.x + f1.y;
        }
        rs0 += __shfl_xor_sync(0xffffffffu, rs0, 1);
        rs0 += __shfl_xor_sync(0xffffffffu, rs0, 2);
        rs1 += __shfl_xor_sync(0xffffffffu, rs1, 1);
        rs1 += __shfl_xor_sync(0xffffffffu, rs1, 2);
        l0 = l0 * al0 + rs0;  l1 = l1 * al1 + rs1;
        m0r = mn0;  m1r = mn1;
        #pragma unroll
        for (int nt = 0; nt < 8; nt++) {
            o[nt][0] *= al0; o[nt][1] *= al0;
            o[nt][2] *= al1; o[nt][3] *= al1;
        }

        // ---- O += P V ----
        #pragma unroll
        for (int kk = 0; kk < 4; kk++) {
            uint32_t kb = (uint32_t)(kk * 32);
            #pragma unroll
            for (int p = 0; p < 4; p++) {
                uint32_t vh0, vh1, vh2, vh3;
                ldmx4(vh0, vh1, vh2, vh3, kvb + TILE_B + bRowOff[p] + kb);
                mma_f16(o[2*p],   pe[2*kk][0], pe[2*kk][1], pe[2*kk+1][0], pe[2*kk+1][1],
                        vh0, vh1);
                mma_f16(o[2*p+1], pe[2*kk][0], pe[2*kk][1], pe[2*kk+1][0], pe[2*kk+1][1],
                        vh2, vh3);
            }
        }

        __syncthreads();   // all warps done reading kt's buffer (next iter overwrites)
    }

    const int row0 = wid*16 + g;
    if (nchunks == 1) {
        float rc0 = 1.f / l0, rc1 = 1.f / l1;
        #pragma unroll
        for (int nt = 0; nt < 8; nt++) {
            int col = nt*8 + 2*tq;
            *reinterpret_cast<float2*>(&out[((size_t)b*T_ + qp*128 + row0) * H_ + col]) =
                make_float2(o[nt][0]*rc0, o[nt][1]*rc0);
            *reinterpret_cast<float2*>(&out[((size_t)b*T_ + qp*128 + row0 + 8) * H_ + col]) =
                make_float2(o[nt][2]*rc1, o[nt][3]*rc1);
        }
    } else {
        const int part = (b*16 + qp)*4 + chunk;
        float* Op = g_Opart + (size_t)part * 128 * 64;
        #pragma unroll
        for (int nt = 0; nt < 8; nt++) {
            int col = nt*8 + 2*tq;
            *reinterpret_cast<float2*>(&Op[(row0)     * 64 + col]) = make_float2(o[nt][0], o[nt][1]);
            *reinterpret_cast<float2*>(&Op[(row0 + 8) * 64 + col]) = make_float2(o[nt][2], o[nt][3]);
        }
        if (tq == 0) {
            g_mpart[part*128 + row0]     = m0r;
            g_mpart[part*128 + row0 + 8] = m1r;
            g_lpart[part*128 + row0]     = l0;
            g_lpart[part*128 + row0 + 8] = l1;
        }
    }
}

// ---------------------------------------------------------------------------
// Merge: combine chunk partials per (b, qp) for qp >= 4 (base-2 weights).
// grid (12, B, 8): 128 rows per (b,qp) split into 8 groups of 16.
// ---------------------------------------------------------------------------
__global__ __launch_bounds__(256) void attn_merge_kernel(float* __restrict__ out)
{
    const int qp = blockIdx.x + 4, b = blockIdx.y;
    const int nc = (2*qp + 9) >> 3;
    const int r  = (int)blockIdx.z * 16 + (threadIdx.x >> 4);  // 0..127
    const int cb = (threadIdx.x & 15) * 4;
    const int pbase = (b*16 + qp)*4;

    float m = -3.0e4f;
    #pragma unroll
    for (int c = 0; c < 4; c++)
        if (c < nc) m = fmaxf(m, g_mpart[(pbase + c)*128 + r]);
    float w[4];
    float l = 0.f;
    #pragma unroll
    for (int c = 0; c < 4; c++) {
        if (c < nc) {
            w[c] = ex2f(g_mpart[(pbase + c)*128 + r] - m);
            l += w[c] * g_lpart[(pbase + c)*128 + r];
        } else w[c] = 0.f;
    }
    float inv = 1.f / l;

    float4 acc = make_float4(0.f, 0.f, 0.f, 0.f);
    #pragma unroll
    for (int c = 0; c < 4; c++) {
        if (c < nc) {
            float4 v = *reinterpret_cast<const float4*>(
                &g_Opart[((size_t)(pbase + c)*128 + r)*64 + cb]);
            acc.x += w[c]*v.x; acc.y += w[c]*v.y;
            acc.z += w[c]*v.z; acc.w += w[c]*v.w;
        }
    }
    acc.x *= inv; acc.y *= inv; acc.z *= inv; acc.w *= inv;
    *reinterpret_cast<float4*>(&out[((size_t)b*T_ + qp*128 + r)*H_ + cb]) = acc;
}

extern "C" void kernel_launch(void* const* d_in, const int* in_sizes, int n_in,
                              void* d_out, int out_size)
{
    const float* x  = (const float*)d_in[0];
    const float* Wq = (const float*)d_in[1];
    const float* Wk = (const float*)d_in[2];
    const float* Wv = (const float*)d_in[3];
    float* out = (float*)d_out;

    cudaFuncSetAttribute(proj_gemm_kernel,
                         cudaFuncAttributeMaxDynamicSharedMemorySize, SM_TOT);
    cudaFuncSetAttribute(attn_part_kernel,
                         cudaFuncAttributeMaxDynamicSharedMemorySize, ASM_TOT);

    prep_B_kernel<<<(192 * 1024) / 256, 256>>>(Wq, Wk, Wv);
    proj_gemm_kernel<<<(B_ * T_) / 128, 512, SM_TOT>>>(x);
    attn_part_kernel<<<dim3(40, B_), 256, ASM_TOT>>>(out);
    attn_merge_kernel<<<dim3(12, B_, 8), 256>>>(out);
}

// round 16
// speedup vs baseline: 1.1421x; 1.1043x over previous
#include <cuda_runtime.h>
#include <cuda_bf16.h>
#include <cuda_fp16.h>
#include <math.h>
#include <stdint.h>

#define B_ 8
#define T_ 2048
#define C_ 1024
#define H_ 64
#define CHUNK 8          // KV tiles per attention CTA

// Q post-RoPE, fp16 hi/lo; K post-RoPE fp16 (single); row-major [B*T][64]
__device__ __align__(16) __half g_Qhi[B_*T_*H_];
__device__ __align__(16) __half g_Qlo[B_*T_*H_];
__device__ __align__(16) __half g_Khi[B_*T_*H_];
// V transposed [B][64 h][T], fp16
__device__ __align__(16) __half g_VThi[B_*H_*T_];
// W split bf16 hi/lo, K-major [192][1024]
__device__ __align__(16) __nv_bfloat16 g_Bhi[192*1024];
__device__ __align__(16) __nv_bfloat16 g_Blo[192*1024];
// split-KV partials (qt >= 8 only): part = (b*32 + qt)*4 + chunk
// m tracked in base-2 scaled space (s * scale * log2e)
__device__ __align__(16) float g_Opart[B_*32*4*64*64];
__device__ float g_mpart[B_*32*4*64];
__device__ float g_lpart[B_*32*4*64];

__device__ __forceinline__ uint32_t smem_u32(const void* p) {
    uint32_t a;
    asm("{ .reg .u64 t; cvta.to.shared.u64 t, %1; cvt.u32.u64 %0, t; }" : "=r"(a) : "l"(p));
    return a;
}
__device__ __forceinline__ void ldmx4(uint32_t& r0, uint32_t& r1, uint32_t& r2, uint32_t& r3,
                                      uint32_t addr) {
    asm volatile("ldmatrix.sync.aligned.m8n8.x4.shared.b16 {%0,%1,%2,%3}, [%4];"
                 : "=r"(r0), "=r"(r1), "=r"(r2), "=r"(r3) : "r"(addr));
}
__device__ __forceinline__ void mma_bf16(float* c,
                                         uint32_t a0, uint32_t a1, uint32_t a2, uint32_t a3,
                                         uint32_t b0, uint32_t b1) {
    asm volatile("mma.sync.aligned.m16n8k16.row.col.f32.bf16.bf16.f32 "
                 "{%0,%1,%2,%3}, {%4,%5,%6,%7}, {%8,%9}, {%0,%1,%2,%3};"
                 : "+f"(c[0]), "+f"(c[1]), "+f"(c[2]), "+f"(c[3])
                 : "r"(a0), "r"(a1), "r"(a2), "r"(a3), "r"(b0), "r"(b1));
}
__device__ __forceinline__ void mma_f16(float* c,
                                        uint32_t a0, uint32_t a1, uint32_t a2, uint32_t a3,
                                        uint32_t b0, uint32_t b1) {
    asm volatile("mma.sync.aligned.m16n8k16.row.col.f32.f16.f16.f32 "
                 "{%0,%1,%2,%3}, {%4,%5,%6,%7}, {%8,%9}, {%0,%1,%2,%3};"
                 : "+f"(c[0]), "+f"(c[1]), "+f"(c[2]), "+f"(c[3])
                 : "r"(a0), "r"(a1), "r"(a2), "r"(a3), "r"(b0), "r"(b1));
}
__device__ __forceinline__ uint32_t bf16x2(float a, float b) {
    __nv_bfloat16 h0 = __float2bfloat16(a), h1 = __float2bfloat16(b);
    return (uint32_t)__bfloat16_as_ushort(h0) | ((uint32_t)__bfloat16_as_ushort(h1) << 16);
}
__device__ __forceinline__ float bf16lo_res(float v) {
    return v - __bfloat162float(__float2bfloat16(v));
}
__device__ __forceinline__ uint32_t h2pack(float a, float b) {
    __half2 h = __floats2half2_rn(a, b);
    return *reinterpret_cast<uint32_t*>(&h);
}
__device__ __forceinline__ float h_lo_res(float v) {
    return v - __half2float(__float2half_rn(v));
}
__device__ __forceinline__ float ex2f(float x) {
    float r; asm("ex2.approx.f32 %0, %1;" : "=f"(r) : "f"(x)); return r;
}
__device__ __forceinline__ uint32_t ex2_h2(uint32_t x) {
    uint32_t r; asm("ex2.approx.f16x2 %0, %1;" : "=r"(r) : "r"(x)); return r;
}
__device__ __forceinline__ float2 h2f2(uint32_t x) {
    __half2 h = *reinterpret_cast<__half2*>(&x);
    return __half22float2(h);
}
#define CP_A16(dst, src) \
    asm volatile("cp.async.cg.shared.global [%0], [%1], 16;" :: "r"(dst), "l"(src))
#define CP_COMMIT() asm volatile("cp.async.commit_group;" ::: "memory")
#define CP_WAIT0()  asm volatile("cp.async.wait_group 0;" ::: "memory")
#define CP_WAIT1()  asm volatile("cp.async.wait_group 1;" ::: "memory")

// ---------------------------------------------------------------------------
// Prep: split W{q,k,v} into bf16 hi/lo, K-major [192][1024]
// ---------------------------------------------------------------------------
__global__ __launch_bounds__(256) void prep_B_kernel(
    const float* __restrict__ Wq, const float* __restrict__ Wk, const float* __restrict__ Wv)
{
    int idx = blockIdx.x * 256 + threadIdx.x;
    int n = idx >> 10, k = idx & 1023;
    const float* W = (n < 64) ? Wq : (n < 128) ? Wk : Wv;
    float v = W[k * 64 + (n & 63)];
    __nv_bfloat16 h = __float2bfloat16(v);
    g_Bhi[idx] = h;
    g_Blo[idx] = __float2bfloat16(v - __bfloat162float(h));
}

// ---------------------------------------------------------------------------
// Projection GEMM (HMMA bf16 hi/lo split) with FRAGMENT REUSE:
// per ks load Ahi,Bhi once -> p0 (Ahi*Bhi); load Alo -> p2 (Alo*Bhi, Bhi
// still live); load Blo -> p1 (Ahi*Blo, Ahi still live). 10 LDSM/ks vs 15.
// M=128 x N=192 per CTA, 16 warps. Epilogue: RoPE; Q fp16 hi/lo, K fp16,
// V fp16 transposed.
// ---------------------------------------------------------------------------
#define PA_STR 72
#define SM_AHI 0
#define SM_ALO (128*PA_STR*2)
#define SM_BHI (2*128*PA_STR*2)
#define SM_BLO (SM_BHI + 192*PA_STR*2)
#define SM_TOT (SM_BLO + 192*PA_STR*2)

__global__ __launch_bounds__(512) void proj_gemm_kernel(const float* __restrict__ x)
{
    extern __shared__ char smem[];
    const uint32_t sbase = smem_u32(smem);
    const int tid    = threadIdx.x;
    const int wid    = tid >> 5;
    const int lane   = tid & 31;
    const int warp_m = wid >> 2;
    const int warp_n = wid & 3;
    const int m0     = blockIdx.x * 128;

    uint32_t aOff[2], bOff[3];
    {
        int mlo = (lane >> 3) & 1, khi = (lane >> 4) & 1, r8 = lane & 7;
        #pragma unroll
        for (int mt = 0; mt < 2; mt++)
            aOff[mt] = (uint32_t)((warp_m*32 + mt*16 + mlo*8 + r8) * (PA_STR*2) + khi*16);
        #pragma unroll
        for (int p = 0; p < 3; p++)
            bOff[p] = (uint32_t)((warp_n*48 + p*16 + khi*8 + r8) * (PA_STR*2) + mlo*16);
    }

    float acc[2][6][4];
    #pragma unroll
    for (int mt = 0; mt < 2; mt++)
        #pragma unroll
        for (int nt = 0; nt < 6; nt++)
            #pragma unroll
            for (int q = 0; q < 4; q++) acc[mt][nt][q] = 0.f;

    #pragma unroll 1
    for (int c = 0; c < 16; c++) {
        const int kc = c * 64;
        if (c > 0) __syncthreads();

        #pragma unroll
        for (int it = tid; it < 2048; it += 512) {
            int r = it >> 4, q = it & 15;
            float4 f = *reinterpret_cast<const float4*>(x + (size_t)(m0 + r) * C_ + kc + q*4);
            uint32_t h0 = bf16x2(f.x, f.y), h1 = bf16x2(f.z, f.w);
            uint32_t l0 = bf16x2(bf16lo_res(f.x), bf16lo_res(f.y));
            uint32_t l1 = bf16x2(bf16lo_res(f.z), bf16lo_res(f.w));
            uint32_t off = (uint32_t)(r * (PA_STR*2) + q * 8);
            *reinterpret_cast<uint2*>(smem + SM_AHI + off) = make_uint2(h0, h1);
            *reinterpret_cast<uint2*>(smem + SM_ALO + off) = make_uint2(l0, l1);
        }
        #pragma unroll
        for (int it = tid; it < 1536; it += 512) {
            int n = it >> 3, s = it & 7;
            uint32_t off = (uint32_t)(n * (PA_STR*2) + s * 16);
            *reinterpret_cast<uint4*>(smem + SM_BHI + off) =
                *reinterpret_cast<const uint4*>(g_Bhi + (size_t)n * 1024 + kc + s*8);
            *reinterpret_cast<uint4*>(smem + SM_BLO + off) =
                *reinterpret_cast<const uint4*>(g_Blo + (size_t)n * 1024 + kc + s*8);
        }
        __syncthreads();

        #pragma unroll
        for (int ks = 0; ks < 4; ks++) {
            uint32_t kb = (uint32_t)(ks * 32);

            // load Ahi + Bhi once
            uint32_t ah[2][4];
            #pragma unroll
            for (int mt = 0; mt < 2; mt++)
                ldmx4(ah[mt][0], ah[mt][1], ah[mt][2], ah[mt][3],
                      sbase + SM_AHI + aOff[mt] + kb);
            uint32_t bh[6][2];
            #pragma unroll
            for (int p = 0; p < 3; p++) {
                uint32_t r0, r1, r2, r3;
                ldmx4(r0, r1, r2, r3, sbase + SM_BHI + bOff[p] + kb);
                bh[p*2][0] = r0; bh[p*2][1] = r1;
                bh[p*2+1][0] = r2; bh[p*2+1][1] = r3;
            }
            // p0: Ahi * Bhi
            #pragma unroll
            for (int mt = 0; mt < 2; mt++)
                #pragma unroll
                for (int nt = 0; nt < 6; nt++)
                    mma_bf16(acc[mt][nt], ah[mt][0], ah[mt][1], ah[mt][2], ah[mt][3],
                             bh[nt][0], bh[nt][1]);

            // p2: Alo * Bhi  (Bhi reused)
            {
                uint32_t al[2][4];
                #pragma unroll
                for (int mt = 0; mt < 2; mt++)
                    ldmx4(al[mt][0], al[mt][1], al[mt][2], al[mt][3],
                          sbase + SM_ALO + aOff[mt] + kb);
                #pragma unroll
                for (int mt = 0; mt < 2; mt++)
                    #pragma unroll
                    for (int nt = 0; nt < 6; nt++)
                        mma_bf16(acc[mt][nt], al[mt][0], al[mt][1], al[mt][2], al[mt][3],
                                 bh[nt][0], bh[nt][1]);
            }
            // p1: Ahi * Blo  (Ahi reused)
            {
                uint32_t bl[6][2];
                #pragma unroll
                for (int p = 0; p < 3; p++) {
                    uint32_t r0, r1, r2, r3;
                    ldmx4(r0, r1, r2, r3, sbase + SM_BLO + bOff[p] + kb);
                    bl[p*2][0] = r0; bl[p*2][1] = r1;
                    bl[p*2+1][0] = r2; bl[p*2+1][1] = r3;
                }
                #pragma unroll
                for (int mt = 0; mt < 2; mt++)
                    #pragma unroll
                    for (int nt = 0; nt < 6; nt++)
                        mma_bf16(acc[mt][nt], ah[mt][0], ah[mt][1], ah[mt][2], ah[mt][3],
                                 bl[nt][0], bl[nt][1]);
            }
        }
    }

    const int g  = lane >> 2;
    const int tq = lane & 3;
    #pragma unroll
    for (int mt = 0; mt < 2; mt++) {
        int row0 = m0 + warp_m*32 + mt*16 + g;
        int rows[2] = { row0, row0 + 8 };
        #pragma unroll
        for (int nt = 0; nt < 6; nt++) {
            int col = warp_n*48 + nt*8 + 2*tq;
            int mat = col >> 6;
            int col_in = col & 63;
            if (mat < 2) {
                int pi = col_in >> 1;
                float inv = powf(10000.f, -(float)pi * (1.f / 32.f));
                #pragma unroll
                for (int rg = 0; rg < 2; rg++) {
                    int t = rows[rg] & (T_ - 1);
                    float sn, cs;
                    sincosf((float)t * inv, &sn, &cs);
                    float a0 = acc[mt][nt][rg*2], a1 = acc[mt][nt][rg*2 + 1];
                    float v0 = a0*cs - a1*sn, v1 = a1*cs + a0*sn;
                    size_t base = (size_t)rows[rg] * H_ + col_in;
                    if (mat == 0) {
                        *reinterpret_cast<uint32_t*>(&g_Qhi[base]) = h2pack(v0, v1);
                        *reinterpret_cast<uint32_t*>(&g_Qlo[base]) =
                            h2pack(h_lo_res(v0), h_lo_res(v1));
                    } else {
                        *reinterpret_cast<uint32_t*>(&g_Khi[base]) = h2pack(v0, v1);
                    }
                }
            } else {
                #pragma unroll
                for (int rg = 0; rg < 2; rg++) {
                    int bb = rows[rg] >> 11, tt = rows[rg] & (T_ - 1);
                    #pragma unroll
                    for (int e = 0; e < 2; e++) {
                        float v = acc[mt][nt][rg*2 + e];
                        size_t idx = ((size_t)bb * H_ + (col_in + e)) * T_ + tt;
                        g_VThi[idx] = __float2half_rn(v);
                    }
                }
            }
        }
    }
}

// ---------------------------------------------------------------------------
// Split-KV attention partial (R13 winner, unchanged): S = Qh*Kh + Ql*Kh;
// PV = Ph*Vh; base-2 softmax via ex2.f16x2; double-buffered KV cp.async.
// smem: Q hi/lo + 2x(K,V) = 6 tiles = 55296B -> 4 CTAs/SM.
// ---------------------------------------------------------------------------
#define ASTR   72
#define TILE_B (64*ASTR*2)
#define AQHI   0
#define AQLO   TILE_B
#define AKV0   (2*TILE_B)           // K, V  (buffer 0)
#define AKV1   (4*TILE_B)           // K, V  (buffer 1)
#define ASM_TOT (6*TILE_B)          // 55296

#define SCALE_L2E 0.1803368801f     // 0.125 * log2(e)
#define MASK_NEG  (-3.0e4f)

__device__ __forceinline__ void stage_kv(uint32_t sdst, int b, int kt, int tid) {
    const __half* Kh = g_Khi + ((size_t)b * T_ + kt*64) * H_;
    #pragma unroll
    for (int it = tid; it < 512; it += 128) {
        int r = it >> 3, s = it & 7;
        uint32_t off = (uint32_t)(r * (ASTR*2) + s*16);
        CP_A16(sdst + off, Kh + r*64 + s*8);
        size_t vsrc = ((size_t)b * H_ + r) * T_ + kt*64 + s*8;
        CP_A16(sdst + TILE_B + off, g_VThi + vsrc);
    }
}

__global__ __launch_bounds__(128, 4) void attn_part_kernel(float* __restrict__ out)
{
    extern __shared__ char smem[];
    const uint32_t sbase = smem_u32(smem);
    const int tid  = threadIdx.x;
    const int wid  = tid >> 5;
    const int lane = tid & 31;
    const int b    = blockIdx.y;
    const int r8   = lane & 7;
    const int mlo  = (lane >> 3) & 1;
    const int khi  = (lane >> 4) & 1;
    const int g    = lane >> 2;
    const int tq   = lane & 3;

    int qt = 0, chunk = 0;
    {
        int bx = blockIdx.x, acc = 0;
        #pragma unroll 1
        for (int q = 0; q < 32; q++) {
            int nc = (q >> 3) + 1;
            if (bx < acc + nc) { qt = q; chunk = bx - acc; break; }
            acc += nc;
        }
    }
    const int kt0 = chunk * CHUNK;
    const int kt1 = (kt0 + CHUNK - 1 < qt) ? (kt0 + CHUNK - 1) : qt;

    const uint32_t aRowOff = (uint32_t)((wid*16 + mlo*8 + r8) * (ASTR*2) + khi*16);
    uint32_t bRowOff[4];
    #pragma unroll
    for (int p = 0; p < 4; p++)
        bRowOff[p] = (uint32_t)((p*16 + khi*8 + r8) * (ASTR*2) + mlo*16);

    // stage Q + first KV tile (group 0)
    {
        const __half* Qh = g_Qhi + ((size_t)b * T_ + qt*64) * H_;
        const __half* Ql = g_Qlo + ((size_t)b * T_ + qt*64) * H_;
        #pragma unroll
        for (int it = tid; it < 512; it += 128) {
            int r = it >> 3, s = it & 7;
            uint32_t off = (uint32_t)(r * (ASTR*2) + s*16);
            CP_A16(sbase + AQHI + off, Qh + r*64 + s*8);
            CP_A16(sbase + AQLO + off, Ql + r*64 + s*8);
        }
        stage_kv(sbase + AKV0, b, kt0, tid);
        CP_COMMIT();
    }

    float m0r = MASK_NEG, m1r = MASK_NEG, l0 = 0.f, l1 = 0.f;
    float o[8][4];
    #pragma unroll
    for (int nt = 0; nt < 8; nt++)
        #pragma unroll
        for (int q = 0; q < 4; q++) o[nt][q] = 0.f;

    #pragma unroll 1
    for (int kt = kt0; kt <= kt1; kt++) {
        const uint32_t kvb = sbase + (((kt - kt0) & 1) ? AKV1 : AKV0);

        if (kt < kt1) {
            stage_kv(sbase + (((kt + 1 - kt0) & 1) ? AKV1 : AKV0), b, kt + 1, tid);
            CP_COMMIT();
            CP_WAIT1();
        } else {
            CP_WAIT0();
        }
        __syncthreads();

        // ---- S = Q K^T (2 passes: Qh*Kh + Ql*Kh) ----
        float s_[8][4];
        #pragma unroll
        for (int nt = 0; nt < 8; nt++)
            #pragma unroll
            for (int q = 0; q < 4; q++) s_[nt][q] = 0.f;

        #pragma unroll
        for (int ks = 0; ks < 4; ks++) {
            uint32_t kb = (uint32_t)(ks * 32);
            uint32_t qh0, qh1, qh2, qh3, ql0, ql1, ql2, ql3;
            ldmx4(qh0, qh1, qh2, qh3, sbase + AQHI + aRowOff + kb);
            ldmx4(ql0, ql1, ql2, ql3, sbase + AQLO + aRowOff + kb);
            #pragma unroll
            for (int p = 0; p < 4; p++) {
                uint32_t kh0, kh1, kh2, kh3;
                ldmx4(kh0, kh1, kh2, kh3, kvb + bRowOff[p] + kb);
                mma_f16(s_[2*p],   qh0, qh1, qh2, qh3, kh0, kh1);
                mma_f16(s_[2*p+1], qh0, qh1, qh2, qh3, kh2, kh3);
                mma_f16(s_[2*p],   ql0, ql1, ql2, ql3, kh0, kh1);
                mma_f16(s_[2*p+1], ql0, ql1, ql2, ql3, kh2, kh3);
            }
        }

        // base-2 scale + causal mask
        #pragma unroll
        for (int nt = 0; nt < 8; nt++)
            #pragma unroll
            for (int q = 0; q < 4; q++) s_[nt][q] *= SCALE_L2E;
        if (kt == qt) {
            int qr0 = qt*64 + wid*16 + g;
            #pragma unroll
            for (int nt = 0; nt < 8; nt++) {
                int kc0 = kt*64 + nt*8 + 2*tq;
                if (kc0     > qr0)     s_[nt][0] = MASK_NEG;
                if (kc0 + 1 > qr0)     s_[nt][1] = MASK_NEG;
                if (kc0     > qr0 + 8) s_[nt][2] = MASK_NEG;
                if (kc0 + 1 > qr0 + 8) s_[nt][3] = MASK_NEG;
            }
        }

        // ---- online softmax (base-2; p emerges packed fp16) ----
        float mx0 = MASK_NEG, mx1 = MASK_NEG;
        #pragma unroll
        for (int nt = 0; nt < 8; nt++) {
            mx0 = fmaxf(mx0, fmaxf(s_[nt][0], s_[nt][1]));
            mx1 = fmaxf(mx1, fmaxf(s_[nt][2], s_[nt][3]));
        }
        mx0 = fmaxf(mx0, __shfl_xor_sync(0xffffffffu, mx0, 1));
        mx0 = fmaxf(mx0, __shfl_xor_sync(0xffffffffu, mx0, 2));
        mx1 = fmaxf(mx1, __shfl_xor_sync(0xffffffffu, mx1, 1));
        mx1 = fmaxf(mx1, __shfl_xor_sync(0xffffffffu, mx1, 2));
        float mn0 = fmaxf(m0r, mx0), mn1 = fmaxf(m1r, mx1);
        float al0 = ex2f(m0r - mn0), al1 = ex2f(m1r - mn1);

        uint32_t pe[8][2];
        float rs0 = 0.f, rs1 = 0.f;
        #pragma unroll
        for (int nt = 0; nt < 8; nt++) {
            pe[nt][0] = ex2_h2(h2pack(s_[nt][0] - mn0, s_[nt][1] - mn0));
            pe[nt][1] = ex2_h2(h2pack(s_[nt][2] - mn1, s_[nt][3] - mn1));
            float2 f0 = h2f2(pe[nt][0]);
            float2 f1 = h2f2(pe[nt][1]);
            rs0 += f0.x + f0.y;
            rs1 += f1.x + f1.y;
        }
        rs0 += __shfl_xor_sync(0xffffffffu, rs0, 1);
        rs0 += __shfl_xor_sync(0xffffffffu, rs0, 2);
        rs1 += __shfl_xor_sync(0xffffffffu, rs1, 1);
        rs1 += __shfl_xor_sync(0xffffffffu, rs1, 2);
        l0 = l0 * al0 + rs0;  l1 = l1 * al1 + rs1;
        m0r = mn0;  m1r = mn1;
        #pragma unroll
        for (int nt = 0; nt < 8; nt++) {
            o[nt][0] *= al0; o[nt][1] *= al0;
            o[nt][2] *= al1; o[nt][3] *= al1;
        }

        // ---- O += P V ----
        #pragma unroll
        for (int kk = 0; kk < 4; kk++) {
            uint32_t kb = (uint32_t)(kk * 32);
            #pragma unroll
            for (int p = 0; p < 4; p++) {
                uint32_t vh0, vh1, vh2, vh3;
                ldmx4(vh0, vh1, vh2, vh3, kvb + TILE_B + bRowOff[p] + kb);
                mma_f16(o[2*p],   pe[2*kk][0], pe[2*kk][1], pe[2*kk+1][0], pe[2*kk+1][1],
                        vh0, vh1);
                mma_f16(o[2*p+1], pe[2*kk][0], pe[2*kk][1], pe[2*kk+1][0], pe[2*kk+1][1],
                        vh2, vh3);
            }
        }

        __syncthreads();
    }

    const int row0 = wid*16 + g;
    if (qt < 8) {
        float rc0 = 1.f / l0, rc1 = 1.f / l1;
        #pragma unroll
        for (int nt = 0; nt < 8; nt++) {
            int col = nt*8 + 2*tq;
            *reinterpret_cast<float2*>(&out[((size_t)b*T_ + qt*64 + row0) * H_ + col]) =
                make_float2(o[nt][0]*rc0, o[nt][1]*rc0);
            *reinterpret_cast<float2*>(&out[((size_t)b*T_ + qt*64 + row0 + 8) * H_ + col]) =
                make_float2(o[nt][2]*rc1, o[nt][3]*rc1);
        }
    } else {
        const int part = (b*32 + qt)*4 + chunk;
        float* Op = g_Opart + (size_t)part * 64 * 64;
        #pragma unroll
        for (int nt = 0; nt < 8; nt++) {
            int col = nt*8 + 2*tq;
            *reinterpret_cast<float2*>(&Op[(row0)     * 64 + col]) = make_float2(o[nt][0], o[nt][1]);
            *reinterpret_cast<float2*>(&Op[(row0 + 8) * 64 + col]) = make_float2(o[nt][2], o[nt][3]);
        }
        if (tq == 0) {
            g_mpart[part*64 + row0]     = m0r;
            g_mpart[part*64 + row0 + 8] = m1r;
            g_lpart[part*64 + row0]     = l0;
            g_lpart[part*64 + row0 + 8] = l1;
        }
    }
}

// ---------------------------------------------------------------------------
// Merge: combine chunk partials per (b, qt) for qt >= 8 (base-2 weights).
// ---------------------------------------------------------------------------
__global__ __launch_bounds__(256) void attn_merge_kernel(float* __restrict__ out)
{
    const int qt = blockIdx.x + 8, b = blockIdx.y;
    const int nc = (qt >> 3) + 1;
    const int r  = (int)blockIdx.z * 16 + (threadIdx.x >> 4);  // 0..63
    const int cb = (threadIdx.x & 15) * 4;
    const int pbase = (b*32 + qt)*4;

    float m = -3.0e4f;
    #pragma unroll
    for (int c = 0; c < 4; c++)
        if (c < nc) m = fmaxf(m, g_mpart[(pbase + c)*64 + r]);
    float w[4];
    float l = 0.f;
    #pragma unroll
    for (int c = 0; c < 4; c++) {
        if (c < nc) {
            w[c] = ex2f(g_mpart[(pbase + c)*64 + r] - m);
            l += w[c] * g_lpart[(pbase + c)*64 + r];
        } else w[c] = 0.f;
    }
    float inv = 1.f / l;

    float4 acc = make_float4(0.f, 0.f, 0.f, 0.f);
    #pragma unroll
    for (int c = 0; c < 4; c++) {
        if (c < nc) {
            float4 v = *reinterpret_cast<const float4*>(
                &g_Opart[((size_t)(pbase + c)*64 + r)*64 + cb]);
            acc.x += w[c]*v.x; acc.y += w[c]*v.y;
            acc.z += w[c]*v.z; acc.w += w[c]*v.w;
        }
    }
    acc.x *= inv; acc.y *= inv; acc.z *= inv; acc.w *= inv;
    *reinterpret_cast<float4*>(&out[((size_t)b*T_ + qt*64 + r)*H_ + cb]) = acc;
}

extern "C" void kernel_launch(void* const* d_in, const int* in_sizes, int n_in,
                              void* d_out, int out_size)
{
    const float* x  = (const float*)d_in[0];
    const float* Wq = (const float*)d_in[1];
    const float* Wk = (const float*)d_in[2];
    const float* Wv = (const float*)d_in[3];
    float* out = (float*)d_out;

    cudaFuncSetAttribute(proj_gemm_kernel,
                         cudaFuncAttributeMaxDynamicSharedMemorySize, SM_TOT);
    cudaFuncSetAttribute(attn_part_kernel,
                         cudaFuncAttributeMaxDynamicSharedMemorySize, ASM_TOT);

    prep_B_kernel<<<(192 * 1024) / 256, 256>>>(Wq, Wk, Wv);
    proj_gemm_kernel<<<(B_ * T_) / 128, 512, SM_TOT>>>(x);
    attn_part_kernel<<<dim3(80, B_), 128, ASM_TOT>>>(out);
    attn_merge_kernel<<<dim3(24, B_, 4), 256>>>(out);
}

// round 17
// speedup vs baseline: 1.2318x; 1.0785x over previous
#include <cuda_runtime.h>
#include <cuda_bf16.h>
#include <cuda_fp16.h>
#include <math.h>
#include <stdint.h>

#define B_ 8
#define T_ 2048
#define C_ 1024
#define H_ 64
#define CHUNK 8          // KV tiles per attention CTA

// Q post-RoPE, fp16 hi/lo; K post-RoPE fp16 (single); row-major [B*T][64]
__device__ __align__(16) __half g_Qhi[B_*T_*H_];
__device__ __align__(16) __half g_Qlo[B_*T_*H_];
__device__ __align__(16) __half g_Khi[B_*T_*H_];
// V transposed [B][64 h][T], fp16
__device__ __align__(16) __half g_VThi[B_*H_*T_];
// W fp16, K-major [192][1024]  (proj GEMM: fp16, 2 passes — x-lo corrected,
// W left at fp16 precision; 2^-11-class error, measured ~1e-4 impact)
__device__ __align__(16) __half g_Bh[192*1024];
// split-KV partials (qt >= 8 only): part = (b*32 + qt)*4 + chunk
// m tracked in base-2 scaled space (s * scale * log2e)
__device__ __align__(16) float g_Opart[B_*32*4*64*64];
__device__ float g_mpart[B_*32*4*64];
__device__ float g_lpart[B_*32*4*64];

__device__ __forceinline__ uint32_t smem_u32(const void* p) {
    uint32_t a;
    asm("{ .reg .u64 t; cvta.to.shared.u64 t, %1; cvt.u32.u64 %0, t; }" : "=r"(a) : "l"(p));
    return a;
}
__device__ __forceinline__ void ldmx4(uint32_t& r0, uint32_t& r1, uint32_t& r2, uint32_t& r3,
                                      uint32_t addr) {
    asm volatile("ldmatrix.sync.aligned.m8n8.x4.shared.b16 {%0,%1,%2,%3}, [%4];"
                 : "=r"(r0), "=r"(r1), "=r"(r2), "=r"(r3) : "r"(addr));
}
__device__ __forceinline__ void mma_f16(float* c,
                                        uint32_t a0, uint32_t a1, uint32_t a2, uint32_t a3,
                                        uint32_t b0, uint32_t b1) {
    asm volatile("mma.sync.aligned.m16n8k16.row.col.f32.f16.f16.f32 "
                 "{%0,%1,%2,%3}, {%4,%5,%6,%7}, {%8,%9}, {%0,%1,%2,%3};"
                 : "+f"(c[0]), "+f"(c[1]), "+f"(c[2]), "+f"(c[3])
                 : "r"(a0), "r"(a1), "r"(a2), "r"(a3), "r"(b0), "r"(b1));
}
__device__ __forceinline__ uint32_t h2pack(float a, float b) {
    __half2 h = __floats2half2_rn(a, b);
    return *reinterpret_cast<uint32_t*>(&h);
}
__device__ __forceinline__ float h_lo_res(float v) {
    return v - __half2float(__float2half_rn(v));
}
__device__ __forceinline__ float ex2f(float x) {
    float r; asm("ex2.approx.f32 %0, %1;" : "=f"(r) : "f"(x)); return r;
}
__device__ __forceinline__ uint32_t ex2_h2(uint32_t x) {
    uint32_t r; asm("ex2.approx.f16x2 %0, %1;" : "=r"(r) : "r"(x)); return r;
}
__device__ __forceinline__ float2 h2f2(uint32_t x) {
    __half2 h = *reinterpret_cast<__half2*>(&x);
    return __half22float2(h);
}
#define CP_A16(dst, src) \
    asm volatile("cp.async.cg.shared.global [%0], [%1], 16;" :: "r"(dst), "l"(src))
#define CP_COMMIT() asm volatile("cp.async.commit_group;" ::: "memory")
#define CP_WAIT0()  asm volatile("cp.async.wait_group 0;" ::: "memory")
#define CP_WAIT1()  asm volatile("cp.async.wait_group 1;" ::: "memory")

// ---------------------------------------------------------------------------
// Prep: W{q,k,v} -> fp16, K-major [192][1024]
// ---------------------------------------------------------------------------
__global__ __launch_bounds__(256) void prep_B_kernel(
    const float* __restrict__ Wq, const float* __restrict__ Wk, const float* __restrict__ Wv)
{
    int idx = blockIdx.x * 256 + threadIdx.x;
    int n = idx >> 10, k = idx & 1023;
    const float* W = (n < 64) ? Wq : (n < 128) ? Wk : Wv;
    g_Bh[idx] = __float2half_rn(W[k * 64 + (n & 63)]);
}

// ---------------------------------------------------------------------------
// Projection GEMM (HMMA fp16, 2 passes with fragment reuse):
// per ks: load Ahi + Bh -> p0 (Ahi*Bh); load Alo -> p1 (Alo*Bh, Bh reused).
// 7 LDSM + 24 MMA per ks. M=128 x N=192 per CTA, 16 warps.
// Epilogue: RoPE; Q fp16 hi/lo, K fp16, V fp16 transposed.
// ---------------------------------------------------------------------------
#define PA_STR 72
#define SM_AHI 0
#define SM_ALO (128*PA_STR*2)             // 18432
#define SM_BH  (2*128*PA_STR*2)           // 36864
#define SM_TOT (SM_BH + 192*PA_STR*2)     // 64512

__global__ __launch_bounds__(512) void proj_gemm_kernel(const float* __restrict__ x)
{
    extern __shared__ char smem[];
    const uint32_t sbase = smem_u32(smem);
    const int tid    = threadIdx.x;
    const int wid    = tid >> 5;
    const int lane   = tid & 31;
    const int warp_m = wid >> 2;
    const int warp_n = wid & 3;
    const int m0     = blockIdx.x * 128;

    uint32_t aOff[2], bOff[3];
    {
        int mlo = (lane >> 3) & 1, khi = (lane >> 4) & 1, r8 = lane & 7;
        #pragma unroll
        for (int mt = 0; mt < 2; mt++)
            aOff[mt] = (uint32_t)((warp_m*32 + mt*16 + mlo*8 + r8) * (PA_STR*2) + khi*16);
        #pragma unroll
        for (int p = 0; p < 3; p++)
            bOff[p] = (uint32_t)((warp_n*48 + p*16 + khi*8 + r8) * (PA_STR*2) + mlo*16);
    }

    float acc[2][6][4];
    #pragma unroll
    for (int mt = 0; mt < 2; mt++)
        #pragma unroll
        for (int nt = 0; nt < 6; nt++)
            #pragma unroll
            for (int q = 0; q < 4; q++) acc[mt][nt][q] = 0.f;

    #pragma unroll 1
    for (int c = 0; c < 16; c++) {
        const int kc = c * 64;
        if (c > 0) __syncthreads();

        // A: x fp32 -> fp16 hi/lo into smem
        #pragma unroll
        for (int it = tid; it < 2048; it += 512) {
            int r = it >> 4, q = it & 15;
            float4 f = *reinterpret_cast<const float4*>(x + (size_t)(m0 + r) * C_ + kc + q*4);
            uint32_t h0 = h2pack(f.x, f.y), h1 = h2pack(f.z, f.w);
            uint32_t l0 = h2pack(h_lo_res(f.x), h_lo_res(f.y));
            uint32_t l1 = h2pack(h_lo_res(f.z), h_lo_res(f.w));
            uint32_t off = (uint32_t)(r * (PA_STR*2) + q * 8);
            *reinterpret_cast<uint2*>(smem + SM_AHI + off) = make_uint2(h0, h1);
            *reinterpret_cast<uint2*>(smem + SM_ALO + off) = make_uint2(l0, l1);
        }
        // B: copy fp16 W tile
        #pragma unroll
        for (int it = tid; it < 1536; it += 512) {
            int n = it >> 3, s = it & 7;
            uint32_t off = (uint32_t)(n * (PA_STR*2) + s * 16);
            *reinterpret_cast<uint4*>(smem + SM_BH + off) =
                *reinterpret_cast<const uint4*>(g_Bh + (size_t)n * 1024 + kc + s*8);
        }
        __syncthreads();

        #pragma unroll
        for (int ks = 0; ks < 4; ks++) {
            uint32_t kb = (uint32_t)(ks * 32);

            uint32_t ah[2][4];
            #pragma unroll
            for (int mt = 0; mt < 2; mt++)
                ldmx4(ah[mt][0], ah[mt][1], ah[mt][2], ah[mt][3],
                      sbase + SM_AHI + aOff[mt] + kb);
            uint32_t bh[6][2];
            #pragma unroll
            for (int p = 0; p < 3; p++) {
                uint32_t r0, r1, r2, r3;
                ldmx4(r0, r1, r2, r3, sbase + SM_BH + bOff[p] + kb);
                bh[p*2][0] = r0; bh[p*2][1] = r1;
                bh[p*2+1][0] = r2; bh[p*2+1][1] = r3;
            }
            // p0: Ahi * Bh
            #pragma unroll
            for (int mt = 0; mt < 2; mt++)
                #pragma unroll
                for (int nt = 0; nt < 6; nt++)
                    mma_f16(acc[mt][nt], ah[mt][0], ah[mt][1], ah[mt][2], ah[mt][3],
                            bh[nt][0], bh[nt][1]);
            // p1: Alo * Bh  (Bh reused)
            {
                uint32_t al[2][4];
                #pragma unroll
                for (int mt = 0; mt < 2; mt++)
                    ldmx4(al[mt][0], al[mt][1], al[mt][2], al[mt][3],
                          sbase + SM_ALO + aOff[mt] + kb);
                #pragma unroll
                for (int mt = 0; mt < 2; mt++)
                    #pragma unroll
                    for (int nt = 0; nt < 6; nt++)
                        mma_f16(acc[mt][nt], al[mt][0], al[mt][1], al[mt][2], al[mt][3],
                                bh[nt][0], bh[nt][1]);
            }
        }
    }

    const int g  = lane >> 2;
    const int tq = lane & 3;
    #pragma unroll
    for (int mt = 0; mt < 2; mt++) {
        int row0 = m0 + warp_m*32 + mt*16 + g;
        int rows[2] = { row0, row0 + 8 };
        #pragma unroll
        for (int nt = 0; nt < 6; nt++) {
            int col = warp_n*48 + nt*8 + 2*tq;
            int mat = col >> 6;
            int col_in = col & 63;
            if (mat < 2) {
                int pi = col_in >> 1;
                float inv = powf(10000.f, -(float)pi * (1.f / 32.f));
                #pragma unroll
                for (int rg = 0; rg < 2; rg++) {
                    int t = rows[rg] & (T_ - 1);
                    float sn, cs;
                    sincosf((float)t * inv, &sn, &cs);
                    float a0 = acc[mt][nt][rg*2], a1 = acc[mt][nt][rg*2 + 1];
                    float v0 = a0*cs - a1*sn, v1 = a1*cs + a0*sn;
                    size_t base = (size_t)rows[rg] * H_ + col_in;
                    if (mat == 0) {
                        *reinterpret_cast<uint32_t*>(&g_Qhi[base]) = h2pack(v0, v1);
                        *reinterpret_cast<uint32_t*>(&g_Qlo[base]) =
                            h2pack(h_lo_res(v0), h_lo_res(v1));
                    } else {
                        *reinterpret_cast<uint32_t*>(&g_Khi[base]) = h2pack(v0, v1);
                    }
                }
            } else {
                #pragma unroll
                for (int rg = 0; rg < 2; rg++) {
                    int bb = rows[rg] >> 11, tt = rows[rg] & (T_ - 1);
                    #pragma unroll
                    for (int e = 0; e < 2; e++) {
                        float v = acc[mt][nt][rg*2 + e];
                        size_t idx = ((size_t)bb * H_ + (col_in + e)) * T_ + tt;
                        g_VThi[idx] = __float2half_rn(v);
                    }
                }
            }
        }
    }
}

// ---------------------------------------------------------------------------
// Split-KV attention partial (R13/R16 winner, unchanged): S = Qh*Kh + Ql*Kh;
// PV = Ph*Vh; base-2 softmax via ex2.f16x2; double-buffered KV cp.async.
// smem: Q hi/lo + 2x(K,V) = 6 tiles = 55296B -> 4 CTAs/SM.
// ---------------------------------------------------------------------------
#define ASTR   72
#define TILE_B (64*ASTR*2)
#define AQHI   0
#define AQLO   TILE_B
#define AKV0   (2*TILE_B)           // K, V  (buffer 0)
#define AKV1   (4*TILE_B)           // K, V  (buffer 1)
#define ASM_TOT (6*TILE_B)          // 55296

#define SCALE_L2E 0.1803368801f     // 0.125 * log2(e)
#define MASK_NEG  (-3.0e4f)

__device__ __forceinline__ void stage_kv(uint32_t sdst, int b, int kt, int tid) {
    const __half* Kh = g_Khi + ((size_t)b * T_ + kt*64) * H_;
    #pragma unroll
    for (int it = tid; it < 512; it += 128) {
        int r = it >> 3, s = it & 7;
        uint32_t off = (uint32_t)(r * (ASTR*2) + s*16);
        CP_A16(sdst + off, Kh + r*64 + s*8);
        size_t vsrc = ((size_t)b * H_ + r) * T_ + kt*64 + s*8;
        CP_A16(sdst + TILE_B + off, g_VThi + vsrc);
    }
}

__global__ __launch_bounds__(128, 4) void attn_part_kernel(float* __restrict__ out)
{
    extern __shared__ char smem[];
    const uint32_t sbase = smem_u32(smem);
    const int tid  = threadIdx.x;
    const int wid  = tid >> 5;
    const int lane = tid & 31;
    const int b    = blockIdx.y;
    const int r8   = lane & 7;
    const int mlo  = (lane >> 3) & 1;
    const int khi  = (lane >> 4) & 1;
    const int g    = lane >> 2;
    const int tq   = lane & 3;

    int qt = 0, chunk = 0;
    {
        int bx = blockIdx.x, acc = 0;
        #pragma unroll 1
        for (int q = 0; q < 32; q++) {
            int nc = (q >> 3) + 1;
            if (bx < acc + nc) { qt = q; chunk = bx - acc; break; }
            acc += nc;
        }
    }
    const int kt0 = chunk * CHUNK;
    const int kt1 = (kt0 + CHUNK - 1 < qt) ? (kt0 + CHUNK - 1) : qt;

    const uint32_t aRowOff = (uint32_t)((wid*16 + mlo*8 + r8) * (ASTR*2) + khi*16);
    uint32_t bRowOff[4];
    #pragma unroll
    for (int p = 0; p < 4; p++)
        bRowOff[p] = (uint32_t)((p*16 + khi*8 + r8) * (ASTR*2) + mlo*16);

    // stage Q + first KV tile (group 0)
    {
        const __half* Qh = g_Qhi + ((size_t)b * T_ + qt*64) * H_;
        const __half* Ql = g_Qlo + ((size_t)b * T_ + qt*64) * H_;
        #pragma unroll
        for (int it = tid; it < 512; it += 128) {
            int r = it >> 3, s = it & 7;
            uint32_t off = (uint32_t)(r * (ASTR*2) + s*16);
            CP_A16(sbase + AQHI + off, Qh + r*64 + s*8);
            CP_A16(sbase + AQLO + off, Ql + r*64 + s*8);
        }
        stage_kv(sbase + AKV0, b, kt0, tid);
        CP_COMMIT();
    }

    float m0r = MASK_NEG, m1r = MASK_NEG, l0 = 0.f, l1 = 0.f;
    float o[8][4];
    #pragma unroll
    for (int nt = 0; nt < 8; nt++)
        #pragma unroll
        for (int q = 0; q < 4; q++) o[nt][q] = 0.f;

    #pragma unroll 1
    for (int kt = kt0; kt <= kt1; kt++) {
        const uint32_t kvb = sbase + (((kt - kt0) & 1) ? AKV1 : AKV0);

        if (kt < kt1) {
            stage_kv(sbase + (((kt + 1 - kt0) & 1) ? AKV1 : AKV0), b, kt + 1, tid);
            CP_COMMIT();
            CP_WAIT1();
        } else {
            CP_WAIT0();
        }
        __syncthreads();

        // ---- S = Q K^T (2 passes: Qh*Kh + Ql*Kh) ----
        float s_[8][4];
        #pragma unroll
        for (int nt = 0; nt < 8; nt++)
            #pragma unroll
            for (int q = 0; q < 4; q++) s_[nt][q] = 0.f;

        #pragma unroll
        for (int ks = 0; ks < 4; ks++) {
            uint32_t kb = (uint32_t)(ks * 32);
            uint32_t qh0, qh1, qh2, qh3, ql0, ql1, ql2, ql3;
            ldmx4(qh0, qh1, qh2, qh3, sbase + AQHI + aRowOff + kb);
            ldmx4(ql0, ql1, ql2, ql3, sbase + AQLO + aRowOff + kb);
            #pragma unroll
            for (int p = 0; p < 4; p++) {
                uint32_t kh0, kh1, kh2, kh3;
                ldmx4(kh0, kh1, kh2, kh3, kvb + bRowOff[p] + kb);
                mma_f16(s_[2*p],   qh0, qh1, qh2, qh3, kh0, kh1);
                mma_f16(s_[2*p+1], qh0, qh1, qh2, qh3, kh2, kh3);
                mma_f16(s_[2*p],   ql0, ql1, ql2, ql3, kh0, kh1);
                mma_f16(s_[2*p+1], ql0, ql1, ql2, ql3, kh2, kh3);
            }
        }

        // base-2 scale + causal mask
        #pragma unroll
        for (int nt = 0; nt < 8; nt++)
            #pragma unroll
            for (int q = 0; q < 4; q++) s_[nt][q] *= SCALE_L2E;
        if (kt == qt) {
            int qr0 = qt*64 + wid*16 + g;
            #pragma unroll
            for (int nt = 0; nt < 8; nt++) {
                int kc0 = kt*64 + nt*8 + 2*tq;
                if (kc0     > qr0)     s_[nt][0] = MASK_NEG;
                if (kc0 + 1 > qr0)     s_[nt][1] = MASK_NEG;
                if (kc0     > qr0 + 8) s_[nt][2] = MASK_NEG;
                if (kc0 + 1 > qr0 + 8) s_[nt][3] = MASK_NEG;
            }
        }

        // ---- online softmax (base-2; p emerges packed fp16) ----
        float mx0 = MASK_NEG, mx1 = MASK_NEG;
        #pragma unroll
        for (int nt = 0; nt < 8; nt++) {
            mx0 = fmaxf(mx0, fmaxf(s_[nt][0], s_[nt][1]));
            mx1 = fmaxf(mx1, fmaxf(s_[nt][2], s_[nt][3]));
        }
        mx0 = fmaxf(mx0, __shfl_xor_sync(0xffffffffu, mx0, 1));
        mx0 = fmaxf(mx0, __shfl_xor_sync(0xffffffffu, mx0, 2));
        mx1 = fmaxf(mx1, __shfl_xor_sync(0xffffffffu, mx1, 1));
        mx1 = fmaxf(mx1, __shfl_xor_sync(0xffffffffu, mx1, 2));
        float mn0 = fmaxf(m0r, mx0), mn1 = fmaxf(m1r, mx1);
        float al0 = ex2f(m0r - mn0), al1 = ex2f(m1r - mn1);

        uint32_t pe[8][2];
        float rs0 = 0.f, rs1 = 0.f;
        #pragma unroll
        for (int nt = 0; nt < 8; nt++) {
            pe[nt][0] = ex2_h2(h2pack(s_[nt][0] - mn0, s_[nt][1] - mn0));
            pe[nt][1] = ex2_h2(h2pack(s_[nt][2] - mn1, s_[nt][3] - mn1));
            float2 f0 = h2f2(pe[nt][0]);
            float2 f1 = h2f2(pe[nt][1]);
            rs0 += f0.x + f0.y;
            rs1 += f1.x + f1.y;
        }
        rs0 += __shfl_xor_sync(0xffffffffu, rs0, 1);
        rs0 += __shfl_xor_sync(0xffffffffu, rs0, 2);
        rs1 += __shfl_xor_sync(0xffffffffu, rs1, 1);
        rs1 += __shfl_xor_sync(0xffffffffu, rs1, 2);
        l0 = l0 * al0 + rs0;  l1 = l1 * al1 + rs1;
        m0r = mn0;  m1r = mn1;
        #pragma unroll
        for (int nt = 0; nt < 8; nt++) {
            o[nt][0] *= al0; o[nt][1] *= al0;
            o[nt][2] *= al1; o[nt][3] *= al1;
        }

        // ---- O += P V ----
        #pragma unroll
        for (int kk = 0; kk < 4; kk++) {
            uint32_t kb = (uint32_t)(kk * 32);
            #pragma unroll
            for (int p = 0; p < 4; p++) {
                uint32_t vh0, vh1, vh2, vh3;
                ldmx4(vh0, vh1, vh2, vh3, kvb + TILE_B + bRowOff[p] + kb);
                mma_f16(o[2*p],   pe[2*kk][0], pe[2*kk][1], pe[2*kk+1][0], pe[2*kk+1][1],
                        vh0, vh1);
                mma_f16(o[2*p+1], pe[2*kk][0], pe[2*kk][1], pe[2*kk+1][0], pe[2*kk+1][1],
                        vh2, vh3);
            }
        }

        __syncthreads();
    }

    const int row0 = wid*16 + g;
    if (qt < 8) {
        float rc0 = 1.f / l0, rc1 = 1.f / l1;
        #pragma unroll
        for (int nt = 0; nt < 8; nt++) {
            int col = nt*8 + 2*tq;
            *reinterpret_cast<float2*>(&out[((size_t)b*T_ + qt*64 + row0) * H_ + col]) =
                make_float2(o[nt][0]*rc0, o[nt][1]*rc0);
            *reinterpret_cast<float2*>(&out[((size_t)b*T_ + qt*64 + row0 + 8) * H_ + col]) =
                make_float2(o[nt][2]*rc1, o[nt][3]*rc1);
        }
    } else {
        const int part = (b*32 + qt)*4 + chunk;
        float* Op = g_Opart + (size_t)part * 64 * 64;
        #pragma unroll
        for (int nt = 0; nt < 8; nt++) {
            int col = nt*8 + 2*tq;
            *reinterpret_cast<float2*>(&Op[(row0)     * 64 + col]) = make_float2(o[nt][0], o[nt][1]);
            *reinterpret_cast<float2*>(&Op[(row0 + 8) * 64 + col]) = make_float2(o[nt][2], o[nt][3]);
        }
        if (tq == 0) {
            g_mpart[part*64 + row0]     = m0r;
            g_mpart[part*64 + row0 + 8] = m1r;
            g_lpart[part*64 + row0]     = l0;
            g_lpart[part*64 + row0 + 8] = l1;
        }
    }
}

// ---------------------------------------------------------------------------
// Merge: combine chunk partials per (b, qt) for qt >= 8 (base-2 weights).
// ---------------------------------------------------------------------------
__global__ __launch_bounds__(256) void attn_merge_kernel(float* __restrict__ out)
{
    const int qt = blockIdx.x + 8, b = blockIdx.y;
    const int nc = (qt >> 3) + 1;
    const int r  = (int)blockIdx.z * 16 + (threadIdx.x >> 4);  // 0..63
    const int cb = (threadIdx.x & 15) * 4;
    const int pbase = (b*32 + qt)*4;

    float m = -3.0e4f;
    #pragma unroll
    for (int c = 0; c < 4; c++)
        if (c < nc) m = fmaxf(m, g_mpart[(pbase + c)*64 + r]);
    float w[4];
    float l = 0.f;
    #pragma unroll
    for (int c = 0; c < 4; c++) {
        if (c < nc) {
            w[c] = ex2f(g_mpart[(pbase + c)*64 + r] - m);
            l += w[c] * g_lpart[(pbase + c)*64 + r];
        } else w[c] = 0.f;
    }
    float inv = 1.f / l;

    float4 acc = make_float4(0.f, 0.f, 0.f, 0.f);
    #pragma unroll
    for (int c = 0; c < 4; c++) {
        if (c < nc) {
            float4 v = *reinterpret_cast<const float4*>(
                &g_Opart[((size_t)(pbase + c)*64 + r)*64 + cb]);
            acc.x += w[c]*v.x; acc.y += w[c]*v.y;
            acc.z += w[c]*v.z; acc.w += w[c]*v.w;
        }
    }
    acc.x *= inv; acc.y *= inv; acc.z *= inv; acc.w *= inv;
    *reinterpret_cast<float4*>(&out[((size_t)b*T_ + qt*64 + r)*H_ + cb]) = acc;
}

extern "C" void kernel_launch(void* const* d_in, const int* in_sizes, int n_in,
                              void* d_out, int out_size)
{
    const float* x  = (const float*)d_in[0];
    const float* Wq = (const float*)d_in[1];
    const float* Wk = (const float*)d_in[2];
    const float* Wv = (const float*)d_in[3];
    float* out = (float*)d_out;

    cudaFuncSetAttribute(proj_gemm_kernel,
                         cudaFuncAttributeMaxDynamicSharedMemorySize, SM_TOT);
    cudaFuncSetAttribute(attn_part_kernel,
                         cudaFuncAttributeMaxDynamicSharedMemorySize, ASM_TOT);

    prep_B_kernel<<<(192 * 1024) / 256, 256>>>(Wq, Wk, Wv);
    proj_gemm_kernel<<<(B_ * T_) / 128, 512, SM_TOT>>>(x);
    attn_part_kernel<<<dim3(80, B_), 128, ASM_TOT>>>(out);
    attn_merge_kernel<<<dim3(24, B_, 4), 256>>>(out);
}